// round 1
// baseline (speedup 1.0000x reference)
#include <cuda_runtime.h>
#include <cuda_bf16.h>
#include <cstdint>

typedef unsigned long long ull;

// ---------------- problem constants ----------------
#define TT   256
#define BB   64
#define EE   512
#define HH   512
#define KK   32
#define TB   (TT*BB)        // 16384
#define NG   4096           // 2 dirs * 4H gate columns
#define STARTT 30
#define ENDT   31
#define NEGV  (-100000.0f)

// ---------------- device scratch (static, no cudaMalloc) ----------------
__device__ float g_xp[(size_t)TB * NG];        // 256 MB, reused by both layers
__device__ float g_h0[(size_t)TB * 1024];      // layer0 output (fwd|bwd)
__device__ float g_h1[(size_t)TB * 1024];      // layer1 output
__device__ float g_feats[(size_t)TB * KK];     // emissions
__device__ ull   g_whh2_0[2 * 256 * 2048];     // packed whh layer0: [dir][k/2][g] float2
__device__ ull   g_whh2_1[2 * 256 * 2048];     // packed whh layer1
__device__ float g_hbuf[2 * 2 * BB * HH];      // [parity][dir][b][h] double buffer
__device__ float g_logz[BB];

// grid barrier state
__device__ unsigned g_cnt = 0;
__device__ unsigned g_gen = 0;

// ---------------- helpers ----------------
__device__ __forceinline__ void ffma2(ull &d, ull a, ull b) {
    asm("fma.rn.f32x2 %0, %1, %2, %0;" : "+l"(d) : "l"(a), "l"(b));
}
__device__ __forceinline__ float2 unpack2(ull v) {
    float2 r;
    asm("mov.b64 {%0, %1}, %2;" : "=f"(r.x), "=f"(r.y) : "l"(v));
    return r;
}
__device__ __forceinline__ float sigmoidf_(float x) { return 1.0f / (1.0f + expf(-x)); }

__device__ __forceinline__ void grid_barrier() {
    __syncthreads();
    if (threadIdx.x == 0) {
        __threadfence();
        unsigned my = *((volatile unsigned*)&g_gen);
        if (atomicAdd(&g_cnt, 1u) == gridDim.x - 1) {
            g_cnt = 0;
            __threadfence();
            *((volatile unsigned*)&g_gen) = my + 1;
        } else {
            while (*((volatile unsigned*)&g_gen) == my) { __nanosleep(32); }
        }
        __threadfence();
    }
    __syncthreads();
}

// ---------------- pack whh -> [dir][k/2][g] float2 over k ----------------
__global__ void k_pack(const float* __restrict__ whh, ull* __restrict__ dst) {
    int i = blockIdx.x * 256 + threadIdx.x;            // i = d*2^20 + g*512 + k
    if (i >= 2 * 2048 * 512) return;
    int k = i & 511;
    int g = (i >> 9) & 2047;
    int d = i >> 20;
    float v = whh[i];
    float* df = (float*)dst;
    df[(((size_t)d * 256 + (k >> 1)) * 2048 + g) * 2 + (k & 1)] = v;
}

// ---------------- SGEMM: C[M=16384][4096] = A[M][KD] * Bw[4096][KD]^T + bias ----
// f32x2 packed over k. 128x64 tile, 256 threads, 8x4 outputs/thread.
template<int KD, bool GATHER>
__global__ __launch_bounds__(256) void k_gemm(
    const float* __restrict__ A, const int* __restrict__ tok,
    const float* __restrict__ Bw, const float* __restrict__ bias,
    float* __restrict__ C)
{
    __shared__ float As[8 * 256];   // [k2][m*2 + half]
    __shared__ float Bs[8 * 128];   // [k2][n*2 + half]
    int tid = threadIdx.x;
    int n0 = blockIdx.x * 64, m0 = blockIdx.y * 128;
    int tn = tid & 15, tm = tid >> 4;

    ull acc[8][4];
#pragma unroll
    for (int i = 0; i < 8; i++)
#pragma unroll
        for (int j = 0; j < 4; j++) acc[i][j] = 0ull;

    for (int k0 = 0; k0 < KD; k0 += 16) {
#pragma unroll
        for (int i = 0; i < 8; i++) {
            int e = tid + i * 256, r = e >> 4, kk = e & 15;
            int row = m0 + r;
            const float* ap = GATHER ? (A + (size_t)tok[row] * KD)
                                     : (A + (size_t)row * KD);
            As[(kk >> 1) * 256 + r * 2 + (kk & 1)] = ap[k0 + kk];
        }
#pragma unroll
        for (int i = 0; i < 4; i++) {
            int e = tid + i * 256, r = e >> 4, kk = e & 15;   // r in 0..63
            Bs[(kk >> 1) * 128 + r * 2 + (kk & 1)] = Bw[(size_t)(n0 + r) * KD + k0 + kk];
        }
        __syncthreads();
#pragma unroll
        for (int k2 = 0; k2 < 8; k2++) {
            ull a2[8], b2[4];
            const ulonglong2* Ap = (const ulonglong2*)&As[k2 * 256 + tm * 16];
#pragma unroll
            for (int i = 0; i < 4; i++) { ulonglong2 v = Ap[i]; a2[2*i] = v.x; a2[2*i+1] = v.y; }
            const ulonglong2* Bp = (const ulonglong2*)&Bs[k2 * 128 + tn * 8];
#pragma unroll
            for (int j = 0; j < 2; j++) { ulonglong2 v = Bp[j]; b2[2*j] = v.x; b2[2*j+1] = v.y; }
#pragma unroll
            for (int i = 0; i < 8; i++)
#pragma unroll
                for (int j = 0; j < 4; j++)
                    ffma2(acc[i][j], a2[i], b2[j]);
        }
        __syncthreads();
    }
#pragma unroll
    for (int i = 0; i < 8; i++) {
        int m = m0 + tm * 8 + i;
#pragma unroll
        for (int j = 0; j < 4; j++) {
            int n = n0 + tn * 4 + j;
            float2 u = unpack2(acc[i][j]);
            C[(size_t)m * NG + n] = u.x + u.y + bias[n];
        }
    }
}

// ---------------- persistent BiLSTM layer kernel ----------------
// grid = 128 CTAs (one per SM, all resident), 256 threads.
// CTA c: dir = c>>6, owns h-columns j0..j0+7 and exactly their 4 gate columns.
__global__ __launch_bounds__(256) void k_lstm(
    const float* __restrict__ xp,   // [TB][4096]: dir*2048 + gt*512 + j (bias included)
    const ull*   __restrict__ whh2, // [dir][k/2][2048] float2-over-k
    float* __restrict__ hout)       // [TB][1024]: dir*512 + j
{
    extern __shared__ float sm[];
    float* h_s   = sm;                  // 64*512
    float* stage = sm + 64 * 512;       // 64*32  (gate pre-acts)
    float* c_s   = sm + 64 * 512 + 64 * 32;  // 64*8

    int tid  = threadIdx.x;
    int cta  = blockIdx.x;
    int dir  = cta >> 6;
    int c64  = cta & 63;
    int j0   = c64 * 8;
    int lane = tid & 31;
    int warp = tid >> 5;
    int gt   = lane & 3;
    int jq   = lane >> 2;
    int col2048 = gt * 512 + (j0 + jq);

    const ull* wcol = whh2 + (size_t)dir * 256 * 2048 + col2048;

    for (int u = tid; u < 64 * 8; u += 256) c_s[u] = 0.0f;
    __syncthreads();

    for (int s = 0; s < TT; s++) {
        int t = dir ? (TT - 1 - s) : s;
        int par = s & 1;

        if (s > 0) {
            const float4* src = (const float4*)(g_hbuf + (size_t)(par * 2 + dir) * BB * HH);
            float4* dst = (float4*)h_s;
            for (int u = tid; u < BB * HH / 4; u += 256) dst[u] = src[u];
        }
        __syncthreads();

        // gate pre-activations: 8 batch rows per thread
        const float* xprow = xp + (size_t)(t * BB) * NG + dir * 2048 + col2048;
        float pre[8];
#pragma unroll
        for (int i = 0; i < 8; i++) pre[i] = xprow[(size_t)(warp + i * 8) * NG];

        if (s > 0) {
            ull acc2[8];
#pragma unroll
            for (int i = 0; i < 8; i++) acc2[i] = 0ull;
            for (int k2 = 0; k2 < 256; k2++) {
                ull w2 = wcol[(size_t)k2 * 2048];
#pragma unroll
                for (int i = 0; i < 8; i++) {
                    ull h2 = *(const ull*)&h_s[(warp + i * 8) * 512 + 2 * k2];
                    ffma2(acc2[i], h2, w2);
                }
            }
#pragma unroll
            for (int i = 0; i < 8; i++) {
                float2 u = unpack2(acc2[i]);
                pre[i] += u.x + u.y;
            }
        }
#pragma unroll
        for (int i = 0; i < 8; i++) stage[(warp + i * 8) * 32 + lane] = pre[i];
        __syncthreads();

        // cell/hidden update: 512 work items, 2 per thread
#pragma unroll
        for (int q = 0; q < 2; q++) {
            int u = tid + q * 256;
            int b = u >> 3, jj = u & 7;
            float4 g4 = *(const float4*)&stage[b * 32 + jj * 4];  // i,f,g,o
            float ig = sigmoidf_(g4.x);
            float fg = sigmoidf_(g4.y);
            float gg = tanhf(g4.z);
            float og = sigmoidf_(g4.w);
            float c = fg * c_s[b * 8 + jj] + ig * gg;
            c_s[b * 8 + jj] = c;
            float h = og * tanhf(c);
            int j = j0 + jj;
            g_hbuf[(size_t)(((par ^ 1) * 2 + dir) * BB + b) * HH + j] = h;
            hout[(size_t)(t * BB + b) * 1024 + dir * 512 + j] = h;
        }
        grid_barrier();
    }
}

// ---------------- emission features: feats = h1 @ lin_w^T + lin_b ----------------
__global__ __launch_bounds__(256) void k_feats(
    const float* __restrict__ h1, const float* __restrict__ lin_w,
    const float* __restrict__ lin_b, float* __restrict__ feats)
{
    extern __shared__ float s[];  // [1024][32] transposed lin_w
    int tid = threadIdx.x;
    for (int i = tid; i < 32 * 1024; i += 256) {
        int c = i & 31, k = i >> 5;
        s[k * 32 + c] = lin_w[c * 1024 + k];
    }
    float bias = lin_b[tid & 31];
    __syncthreads();
    int warp = tid >> 5, lane = tid & 31;
    int rows = TB / gridDim.x;
    int r0 = blockIdx.x * rows;
    for (int r = r0 + warp; r < r0 + rows; r += 8) {
        const float* x = h1 + (size_t)r * 1024;
        float acc = 0.0f;
        for (int k0 = 0; k0 < 1024; k0 += 32) {
            float xv = x[k0 + lane];
#pragma unroll
            for (int kk = 0; kk < 32; kk++) {
                float xs = __shfl_sync(0xffffffffu, xv, kk);
                acc += xs * s[(k0 + kk) * 32 + lane];
            }
        }
        feats[(size_t)r * 32 + lane] = acc + bias;
    }
}

// ---------------- CRF forward (one warp per batch, lane = tag) ----------------
__global__ __launch_bounds__(1024) void k_crf(
    const float* __restrict__ feats, const float* __restrict__ trans,
    const int* __restrict__ tokens, float* __restrict__ logz)
{
    __shared__ float s_tr[32 * 33];
    int tid = threadIdx.x;
    for (int i = tid; i < 1024; i += blockDim.x)
        s_tr[(i >> 5) * 33 + (i & 31)] = trans[i];
    __syncthreads();
    int warp = tid >> 5, lane = tid & 31;
    int b = blockIdx.x * 32 + warp;

    float alpha = (lane == STARTT) ? 0.0f : NEGV;
    for (int t = 0; t < TT; t++) {
        float emit = feats[(size_t)(t * BB + b) * 32 + lane];
        int m = tokens[t * BB + b] > 0;
        float v[32];
        float mx = -3.4e38f;
#pragma unroll
        for (int k = 0; k < 32; k++) {
            float ak = __shfl_sync(0xffffffffu, alpha, k);
            v[k] = ak + s_tr[lane * 33 + k];
            mx = fmaxf(mx, v[k]);
        }
        float ssum = 0.0f;
#pragma unroll
        for (int k = 0; k < 32; k++) ssum += expf(v[k] - mx);
        float nv = mx + logf(ssum) + emit;
        alpha = m ? nv : alpha;
    }
    float val = alpha + s_tr[ENDT * 33 + lane];
    float mx = val;
#pragma unroll
    for (int o = 16; o; o >>= 1) mx = fmaxf(mx, __shfl_xor_sync(0xffffffffu, mx, o));
    float ss = expf(val - mx);
#pragma unroll
    for (int o = 16; o; o >>= 1) ss += __shfl_xor_sync(0xffffffffu, ss, o);
    if (lane == 0) logz[b] = mx + logf(ss);
}

// ---------------- gold score + final reduction ----------------
__global__ void k_final(
    const int* __restrict__ tags, const int* __restrict__ tokens,
    const float* __restrict__ trans, const float* __restrict__ feats,
    const float* __restrict__ logz, const int* __restrict__ lengths,
    float* __restrict__ out)
{
    __shared__ float red[BB];
    int b = threadIdx.x;
    float gold = 0.0f;
    int prev = STARTT;
    for (int t = 0; t < TT; t++) {
        int cur = tags[t * BB + b];
        float m = tokens[t * BB + b] > 0 ? 1.0f : 0.0f;
        gold += m * (trans[cur * 32 + prev] + feats[(size_t)(t * BB + b) * 32 + cur]);
        prev = cur;
    }
    gold += trans[ENDT * 32 + prev];
    red[b] = (logz[b] - gold) / (float)lengths[b];
    __syncthreads();
    if (b == 0) {
        float s = 0.0f;
        for (int i = 0; i < BB; i++) s += red[i];
        out[0] = s;
    }
}

// ---------------- launch ----------------
extern "C" void kernel_launch(void* const* d_in, const int* in_sizes, int n_in,
                              void* d_out, int out_size)
{
    const int*   tokens = (const int*)d_in[0];
    const int*   tags   = (const int*)d_in[1];
    const int*   lens   = (const int*)d_in[2];
    const float* embed  = (const float*)d_in[3];
    const float* wih0   = (const float*)d_in[4];
    const float* whh0   = (const float*)d_in[5];
    const float* b0     = (const float*)d_in[6];
    const float* wih1   = (const float*)d_in[7];
    const float* whh1   = (const float*)d_in[8];
    const float* b1     = (const float*)d_in[9];
    const float* lin_w  = (const float*)d_in[10];
    const float* lin_b  = (const float*)d_in[11];
    const float* trans  = (const float*)d_in[12];
    float* out = (float*)d_out;

    void *p;
    cudaGetSymbolAddress(&p, g_xp);    float* xp    = (float*)p;
    cudaGetSymbolAddress(&p, g_h0);    float* h0    = (float*)p;
    cudaGetSymbolAddress(&p, g_h1);    float* h1    = (float*)p;
    cudaGetSymbolAddress(&p, g_feats); float* feats = (float*)p;
    cudaGetSymbolAddress(&p, g_whh2_0); ull* w2a    = (ull*)p;
    cudaGetSymbolAddress(&p, g_whh2_1); ull* w2b    = (ull*)p;
    cudaGetSymbolAddress(&p, g_logz);  float* logz  = (float*)p;

    const int LSTM_SMEM = (64 * 512 + 64 * 32 + 64 * 8) * 4;   // 141312 B
    cudaFuncSetAttribute(k_lstm, cudaFuncAttributeMaxDynamicSharedMemorySize, LSTM_SMEM);
    cudaFuncSetAttribute(k_feats, cudaFuncAttributeMaxDynamicSharedMemorySize, 131072);

    // pack recurrent weights (float2 over k)
    k_pack<<<8192, 256>>>(whh0, w2a);
    k_pack<<<8192, 256>>>(whh1, w2b);

    dim3 gg(NG / 64, TB / 128);   // (64, 128)

    // layer 0
    k_gemm<EE, true><<<gg, 256>>>(embed, tokens, wih0, b0, xp);
    k_lstm<<<128, 256, LSTM_SMEM>>>(xp, w2a, h0);

    // layer 1
    k_gemm<1024, false><<<gg, 256>>>(h0, tokens, wih1, b1, xp);
    k_lstm<<<128, 256, LSTM_SMEM>>>(xp, w2b, h1);

    // emissions
    k_feats<<<128, 256, 131072>>>(h1, lin_w, lin_b, feats);

    // CRF partition function
    k_crf<<<2, 1024>>>(feats, trans, tokens, logz);

    // gold + loss
    k_final<<<1, BB>>>(tags, tokens, trans, feats, logz, lens, out);
}

// round 2
// speedup vs baseline: 1.5962x; 1.5962x over previous
#include <cuda_runtime.h>
#include <cuda_bf16.h>
#include <cstdint>

typedef unsigned long long ull;

// ---------------- problem constants ----------------
#define TT   256
#define BB   64
#define EE   512
#define HH   512
#define KK   32
#define TB   (TT*BB)        // 16384
#define NG   4096           // 2 dirs * 4H gate columns
#define STARTT 30
#define ENDT   31
#define NEGV  (-100000.0f)

// padded h layout: per row [256 floats | 4 pad | 256 floats | 4 pad] = 524
#define HSTRIDE 524
#define KSOFF   260
#define HBYTES  (BB*HSTRIDE*4)    // 134144, %16==0

// ---------------- device scratch (static, no cudaMalloc) ----------------
__device__ float g_xp[(size_t)TB * NG];        // reused by both layers
__device__ float g_h0[(size_t)TB * 1024];      // layer0 output (fwd|bwd)
__device__ float g_h1[(size_t)TB * 1024];      // layer1 output
__device__ float g_feats[(size_t)TB * KK];     // emissions
__device__ float g_hbuf[2 * 2 * BB * HSTRIDE]; // [parity][dir][b][padded j]
__device__ float g_logz[BB];

// grid barrier state
__device__ unsigned g_cnt = 0;
__device__ unsigned g_gen = 0;

// ---------------- helpers ----------------
__device__ __forceinline__ void ffma2(ull &d, ull a, ull b) {
    asm("fma.rn.f32x2 %0, %1, %2, %0;" : "+l"(d) : "l"(a), "l"(b));
}
__device__ __forceinline__ float2 unpack2(ull v) {
    float2 r;
    asm("mov.b64 {%0, %1}, %2;" : "=f"(r.x), "=f"(r.y) : "l"(v));
    return r;
}
__device__ __forceinline__ float sigmoidf_(float x) { return 1.0f / (1.0f + expf(-x)); }

__device__ __forceinline__ uint32_t s2u(const void* p) {
    uint32_t a;
    asm("{ .reg .u64 t; cvta.to.shared.u64 t, %1; cvt.u32.u64 %0, t; }" : "=r"(a) : "l"(p));
    return a;
}
__device__ __forceinline__ void mwait(uint32_t mbar, uint32_t phase) {
    asm volatile(
        "{\n\t.reg .pred P;\n"
        "W%=:\n\t"
        "mbarrier.try_wait.parity.acquire.cta.shared::cta.b64 P, [%0], %1, 0x989680;\n\t"
        "@P bra D%=;\n\t"
        "bra W%=;\n"
        "D%=:\n\t}"
        :: "r"(mbar), "r"(phase) : "memory");
}

__device__ __forceinline__ void grid_barrier() {
    __syncthreads();
    if (threadIdx.x == 0) {
        __threadfence();
        unsigned my = *((volatile unsigned*)&g_gen);
        if (atomicAdd(&g_cnt, 1u) == gridDim.x - 1) {
            g_cnt = 0;
            __threadfence();
            *((volatile unsigned*)&g_gen) = my + 1;
        } else {
            while (*((volatile unsigned*)&g_gen) == my) { __nanosleep(20); }
        }
        __threadfence();
    }
    __syncthreads();
}

// ---------------- SGEMM: C[16384][4096] = A[M][KD] * Bw[4096][KD]^T + bias ----
// f32x2 packed over k. 128x64 tile, 256 threads, 8x4 outputs/thread.
// Register prefetch double-buffering over k-tiles.
template<int KD, bool GATHER>
__global__ __launch_bounds__(256) void k_gemm(
    const float* __restrict__ A, const int* __restrict__ tok,
    const float* __restrict__ Bw, const float* __restrict__ bias,
    float* __restrict__ C)
{
    __shared__ float As[8 * 256];   // [k2][m*2 + half]
    __shared__ float Bs[8 * 128];   // [k2][n*2 + half]
    int tid = threadIdx.x;
    int n0 = blockIdx.x * 64, m0 = blockIdx.y * 128;
    int tn = tid & 15, tm = tid >> 4;

    // source pointers (+tn element offset baked in)
    const float* aptr[8];
    const float* bptr[4];
#pragma unroll
    for (int i = 0; i < 8; i++) {
        int row = m0 + tm + 16 * i;
        aptr[i] = (GATHER ? (A + (size_t)tok[row] * KD)
                          : (A + (size_t)row * KD)) + tn;
    }
#pragma unroll
    for (int i = 0; i < 4; i++)
        bptr[i] = Bw + (size_t)(n0 + tm + 16 * i) * KD + tn;

    float bb[4];
#pragma unroll
    for (int j = 0; j < 4; j++) bb[j] = bias[n0 + tn * 4 + j];

    ull acc[8][4];
#pragma unroll
    for (int i = 0; i < 8; i++)
#pragma unroll
        for (int j = 0; j < 4; j++) acc[i][j] = 0ull;

    float fa[8], fb[4];
#pragma unroll
    for (int i = 0; i < 8; i++) fa[i] = aptr[i][0];
#pragma unroll
    for (int i = 0; i < 4; i++) fb[i] = bptr[i][0];

    for (int k0 = 0; k0 < KD; k0 += 16) {
#pragma unroll
        for (int i = 0; i < 8; i++)
            As[(tn >> 1) * 256 + (tm + 16 * i) * 2 + (tn & 1)] = fa[i];
#pragma unroll
        for (int i = 0; i < 4; i++)
            Bs[(tn >> 1) * 128 + (tm + 16 * i) * 2 + (tn & 1)] = fb[i];
        __syncthreads();

        if (k0 + 16 < KD) {
#pragma unroll
            for (int i = 0; i < 8; i++) fa[i] = aptr[i][k0 + 16];
#pragma unroll
            for (int i = 0; i < 4; i++) fb[i] = bptr[i][k0 + 16];
        }

#pragma unroll
        for (int k2 = 0; k2 < 8; k2++) {
            ull a2[8], b2[4];
            const ulonglong2* Ap = (const ulonglong2*)&As[k2 * 256 + tm * 16];
#pragma unroll
            for (int i = 0; i < 4; i++) { ulonglong2 v = Ap[i]; a2[2*i] = v.x; a2[2*i+1] = v.y; }
            const ulonglong2* Bp = (const ulonglong2*)&Bs[k2 * 128 + tn * 8];
#pragma unroll
            for (int j = 0; j < 2; j++) { ulonglong2 v = Bp[j]; b2[2*j] = v.x; b2[2*j+1] = v.y; }
#pragma unroll
            for (int i = 0; i < 8; i++)
#pragma unroll
                for (int j = 0; j < 4; j++)
                    ffma2(acc[i][j], a2[i], b2[j]);
        }
        __syncthreads();
    }
#pragma unroll
    for (int i = 0; i < 8; i++) {
        int m = m0 + tm * 8 + i;
        float4 o;
        float2 u;
        u = unpack2(acc[i][0]); o.x = u.x + u.y + bb[0];
        u = unpack2(acc[i][1]); o.y = u.x + u.y + bb[1];
        u = unpack2(acc[i][2]); o.z = u.x + u.y + bb[2];
        u = unpack2(acc[i][3]); o.w = u.x + u.y + bb[3];
        *(float4*)&C[(size_t)m * NG + n0 + tn * 4] = o;
    }
}

// ---------------- persistent BiLSTM layer kernel ----------------
// grid = 128 CTAs (1/SM), 256 threads. CTA c: dir = c>>6, owns h-cols j0..j0+7
// (32 gate columns). Weights resident in SMEM all 256 steps. h exchanged via
// one cp.async.bulk per step into padded smem. Cell state in registers.
// Thread map: lane: c4 = lane&7 (j = j0+c4), ks = (lane>>3)&1 (k half),
//             rg = (warp<<1)|(lane>>4) -> rows rg*4 .. rg*4+3.
__global__ __launch_bounds__(256) void k_lstm(
    const float* __restrict__ xp,   // [TB][4096]: dir*2048 + gt*512 + j (bias incl)
    const float* __restrict__ whh,  // raw [2][2048][512]
    float* __restrict__ hout)       // [TB][1024]: dir*512 + j
{
    extern __shared__ float sm[];
    float* h_s   = sm;                              // BB*HSTRIDE floats (134144 B)
    ull*   w_s   = (ull*)(sm + BB * HSTRIDE);       // 2*4100 ull (65600 B)
    float* stage = (float*)(w_s + 2 * 4100);        // 64*36 floats (9216 B)
    ull*   mbar  = (ull*)(stage + 64 * 36);

    int tid  = threadIdx.x;
    int cta  = blockIdx.x;
    int dir  = cta >> 6;
    int j0   = (cta & 63) * 8;
    int lane = tid & 31, warp = tid >> 5;
    int c4   = lane & 7;
    int ks   = (lane >> 3) & 1;
    int rg   = (warp << 1) | (lane >> 4);

    uint32_t mbar_u = s2u(mbar);
    uint32_t hdst_u = s2u(h_s);
    if (tid == 0) {
        asm volatile("mbarrier.init.shared.b64 [%0], 1;" :: "r"(mbar_u));
    }

    // stage weights into smem: w_s[ks][k2'][cc] ull (k-pairs), cc = jq*4 + gt
    const float* W = whh + (size_t)dir * 2048 * 512;
    for (int e = tid; e < 8192; e += 256) {
        int cc = e & 31, k2g = e >> 5;
        int col = (cc & 3) * 512 + j0 + (cc >> 2);
        float lo = W[(size_t)col * 512 + 2 * k2g];
        float hi = W[(size_t)col * 512 + 2 * k2g + 1];
        ull v;
        asm("mov.b64 %0, {%1,%2};" : "=l"(v) : "f"(lo), "f"(hi));
        w_s[((k2g >> 7) * 4100) + (k2g & 127) * 32 + cc] = v;
    }
    __syncthreads();

    float creg[4] = {0.f, 0.f, 0.f, 0.f};
    const ull* wbase = w_s + ks * 4100 + c4 * 4;

    for (int s = 0; s < TT; s++) {
        int t = dir ? (TT - 1 - s) : s;
        int par = s & 1;

        // kick off the h copy for this step (producer writes fenced by grid barrier)
        if (s > 0 && tid == 0) {
            const float* src = g_hbuf + (size_t)(par * 2 + dir) * BB * HSTRIDE;
            asm volatile("mbarrier.arrive.expect_tx.shared.b64 _, [%0], %1;"
                         :: "r"(mbar_u), "r"((uint32_t)HBYTES));
            asm volatile("cp.async.bulk.shared::cta.global.mbarrier::complete_tx::bytes [%0], [%1], %2, [%3];"
                         :: "r"(hdst_u), "l"(src), "r"((uint32_t)HBYTES), "r"(mbar_u) : "memory");
        }

        // prefetch xp while the TMA copy is in flight (ks0 threads only use it)
        float xpre[4][4];
        if (ks == 0) {
#pragma unroll
            for (int i = 0; i < 4; i++) {
                int b = rg * 4 + i;
                const float* xr = xp + (size_t)(t * BB + b) * NG + dir * 2048 + j0 + c4;
                xpre[i][0] = xr[0];
                xpre[i][1] = xr[512];
                xpre[i][2] = xr[1024];
                xpre[i][3] = xr[1536];
            }
        }

        float af[4][4];
        if (s > 0) {
            mwait(mbar_u, (s - 1) & 1);

            ull acc[4][4];
#pragma unroll
            for (int i = 0; i < 4; i++)
#pragma unroll
                for (int g = 0; g < 4; g++) acc[i][g] = 0ull;

            const float* hb0 = h_s + (rg * 4) * HSTRIDE + ks * KSOFF;
#pragma unroll 4
            for (int q = 0; q < 128; q += 2) {
                ulonglong2 w0 = *(const ulonglong2*)(wbase + q * 32);
                ulonglong2 w1 = *(const ulonglong2*)(wbase + q * 32 + 2);
                ulonglong2 w2 = *(const ulonglong2*)(wbase + (q + 1) * 32);
                ulonglong2 w3 = *(const ulonglong2*)(wbase + (q + 1) * 32 + 2);
#pragma unroll
                for (int i = 0; i < 4; i++) {
                    ulonglong2 h2 = *(const ulonglong2*)(hb0 + i * HSTRIDE + 2 * q);
                    ffma2(acc[i][0], h2.x, w0.x);
                    ffma2(acc[i][1], h2.x, w0.y);
                    ffma2(acc[i][2], h2.x, w1.x);
                    ffma2(acc[i][3], h2.x, w1.y);
                    ffma2(acc[i][0], h2.y, w2.x);
                    ffma2(acc[i][1], h2.y, w2.y);
                    ffma2(acc[i][2], h2.y, w3.x);
                    ffma2(acc[i][3], h2.y, w3.y);
                }
            }
#pragma unroll
            for (int i = 0; i < 4; i++)
#pragma unroll
                for (int g = 0; g < 4; g++) {
                    float2 u = unpack2(acc[i][g]);
                    af[i][g] = u.x + u.y;
                }

            if (ks == 1) {
#pragma unroll
                for (int i = 0; i < 4; i++) {
                    float4 v = make_float4(af[i][0], af[i][1], af[i][2], af[i][3]);
                    *(float4*)&stage[(rg * 4 + i) * 36 + c4 * 4] = v;
                }
            }
        }
        __syncthreads();

        if (ks == 0) {
#pragma unroll
            for (int i = 0; i < 4; i++) {
                int b = rg * 4 + i;
                float p0 = xpre[i][0], p1 = xpre[i][1], p2 = xpre[i][2], p3 = xpre[i][3];
                if (s > 0) {
                    float4 sv = *(const float4*)&stage[b * 36 + c4 * 4];
                    p0 += af[i][0] + sv.x;
                    p1 += af[i][1] + sv.y;
                    p2 += af[i][2] + sv.z;
                    p3 += af[i][3] + sv.w;
                }
                float ig = sigmoidf_(p0);
                float fg = sigmoidf_(p1);
                float gg = tanhf(p2);
                float og = sigmoidf_(p3);
                float c = fg * creg[i] + ig * gg;
                creg[i] = c;
                float h = og * tanhf(c);
                int j = j0 + c4;
                int jpad = (j < 256) ? j : j + 4;
                g_hbuf[(size_t)(((par ^ 1) * 2 + dir) * BB + b) * HSTRIDE + jpad] = h;
                hout[(size_t)(t * BB + b) * 1024 + dir * 512 + j] = h;
            }
        }
        grid_barrier();
    }
}

// ---------------- emission features: feats = h1 @ lin_w^T + lin_b ----------------
__global__ __launch_bounds__(256) void k_feats(
    const float* __restrict__ h1, const float* __restrict__ lin_w,
    const float* __restrict__ lin_b, float* __restrict__ feats)
{
    extern __shared__ float s[];  // [1024][32] transposed lin_w
    int tid = threadIdx.x;
    for (int i = tid; i < 32 * 1024; i += 256) {
        int c = i & 31, k = i >> 5;
        s[k * 32 + c] = lin_w[c * 1024 + k];
    }
    float bias = lin_b[tid & 31];
    __syncthreads();
    int warp = tid >> 5, lane = tid & 31;
    int rows = TB / gridDim.x;
    int r0 = blockIdx.x * rows;
    for (int r = r0 + warp; r < r0 + rows; r += 8) {
        const float* x = h1 + (size_t)r * 1024;
        float acc = 0.0f;
        for (int k0 = 0; k0 < 1024; k0 += 32) {
            float xv = x[k0 + lane];
#pragma unroll
            for (int kk = 0; kk < 32; kk++) {
                float xs = __shfl_sync(0xffffffffu, xv, kk);
                acc += xs * s[(k0 + kk) * 32 + lane];
            }
        }
        feats[(size_t)r * 32 + lane] = acc + bias;
    }
}

// ---------------- CRF forward (one warp per batch, lane = tag) ----------------
__global__ __launch_bounds__(32) void k_crf(
    const float* __restrict__ feats, const float* __restrict__ trans,
    const int* __restrict__ tokens, float* __restrict__ logz)
{
    __shared__ float s_tr[32 * 33];
    int lane = threadIdx.x;
    for (int i = lane; i < 1024; i += 32)
        s_tr[(i >> 5) * 33 + (i & 31)] = trans[i];
    __syncwarp();
    int b = blockIdx.x;

    float alpha = (lane == STARTT) ? 0.0f : NEGV;
    for (int t = 0; t < TT; t++) {
        float emit = feats[(size_t)(t * BB + b) * 32 + lane];
        int m = tokens[t * BB + b] > 0;
        float v[32];
        float mx = -3.4e38f;
#pragma unroll
        for (int k = 0; k < 32; k++) {
            float ak = __shfl_sync(0xffffffffu, alpha, k);
            v[k] = ak + s_tr[lane * 33 + k];
            mx = fmaxf(mx, v[k]);
        }
        float ssum = 0.0f;
#pragma unroll
        for (int k = 0; k < 32; k++) ssum += __expf(v[k] - mx);
        float nv = mx + __logf(ssum) + emit;
        alpha = m ? nv : alpha;
    }
    float val = alpha + s_tr[ENDT * 33 + lane];
    float mx = val;
#pragma unroll
    for (int o = 16; o; o >>= 1) mx = fmaxf(mx, __shfl_xor_sync(0xffffffffu, mx, o));
    float ss = __expf(val - mx);
#pragma unroll
    for (int o = 16; o; o >>= 1) ss += __shfl_xor_sync(0xffffffffu, ss, o);
    if (lane == 0) logz[b] = mx + __logf(ss);
}

// ---------------- gold score + final reduction ----------------
__global__ void k_final(
    const int* __restrict__ tags, const int* __restrict__ tokens,
    const float* __restrict__ trans, const float* __restrict__ feats,
    const float* __restrict__ logz, const int* __restrict__ lengths,
    float* __restrict__ out)
{
    __shared__ float red[BB];
    int b = threadIdx.x;
    float gold = 0.0f;
    int prev = STARTT;
    for (int t = 0; t < TT; t++) {
        int cur = tags[t * BB + b];
        float m = tokens[t * BB + b] > 0 ? 1.0f : 0.0f;
        gold += m * (trans[cur * 32 + prev] + feats[(size_t)(t * BB + b) * 32 + cur]);
        prev = cur;
    }
    gold += trans[ENDT * 32 + prev];
    red[b] = (logz[b] - gold) / (float)lengths[b];
    __syncthreads();
    if (b == 0) {
        float s = 0.0f;
        for (int i = 0; i < BB; i++) s += red[i];
        out[0] = s;
    }
}

// ---------------- launch ----------------
extern "C" void kernel_launch(void* const* d_in, const int* in_sizes, int n_in,
                              void* d_out, int out_size)
{
    const int*   tokens = (const int*)d_in[0];
    const int*   tags   = (const int*)d_in[1];
    const int*   lens   = (const int*)d_in[2];
    const float* embed  = (const float*)d_in[3];
    const float* wih0   = (const float*)d_in[4];
    const float* whh0   = (const float*)d_in[5];
    const float* b0     = (const float*)d_in[6];
    const float* wih1   = (const float*)d_in[7];
    const float* whh1   = (const float*)d_in[8];
    const float* b1     = (const float*)d_in[9];
    const float* lin_w  = (const float*)d_in[10];
    const float* lin_b  = (const float*)d_in[11];
    const float* trans  = (const float*)d_in[12];
    float* out = (float*)d_out;

    void *p;
    cudaGetSymbolAddress(&p, g_xp);    float* xp    = (float*)p;
    cudaGetSymbolAddress(&p, g_h0);    float* h0    = (float*)p;
    cudaGetSymbolAddress(&p, g_h1);    float* h1    = (float*)p;
    cudaGetSymbolAddress(&p, g_feats); float* feats = (float*)p;
    cudaGetSymbolAddress(&p, g_logz);  float* logz  = (float*)p;

    const int LSTM_SMEM = HBYTES + 2 * 4100 * 8 + 64 * 36 * 4 + 16;  // 208976 B
    cudaFuncSetAttribute(k_lstm, cudaFuncAttributeMaxDynamicSharedMemorySize, LSTM_SMEM);
    cudaFuncSetAttribute(k_feats, cudaFuncAttributeMaxDynamicSharedMemorySize, 131072);

    dim3 gg(NG / 64, TB / 128);   // (64, 128)

    // layer 0
    k_gemm<EE, true><<<gg, 256>>>(embed, tokens, wih0, b0, xp);
    k_lstm<<<128, 256, LSTM_SMEM>>>(xp, whh0, h0);

    // layer 1
    k_gemm<1024, false><<<gg, 256>>>(h0, tokens, wih1, b1, xp);
    k_lstm<<<128, 256, LSTM_SMEM>>>(xp, whh1, h1);

    // emissions
    k_feats<<<128, 256, 131072>>>(h1, lin_w, lin_b, feats);

    // CRF partition function
    k_crf<<<BB, 32>>>(feats, trans, tokens, logz);

    // gold + loss
    k_final<<<1, BB>>>(tags, tokens, trans, feats, logz, lens, out);
}

// round 3
// speedup vs baseline: 2.4174x; 1.5145x over previous
#include <cuda_runtime.h>
#include <cuda_bf16.h>
#include <cstdint>

typedef unsigned long long ull;

// ---------------- problem constants ----------------
#define TT   256
#define BB   64
#define EE   512
#define HH   512
#define KK   32
#define TB   (TT*BB)        // 16384
#define NG   4096           // 2 dirs * 4H gate columns
#define STARTT 30
#define ENDT   31
#define NEGV  (-100000.0f)

#define HBYTES  (BB*HH*4)   // 131072

// ---------------- device scratch (static, no cudaMalloc) ----------------
__device__ float g_xp[(size_t)TB * NG];        // reused by both layers
__device__ float g_h0[(size_t)TB * 1024];      // layer0 output (fwd|bwd)
__device__ float g_h1[(size_t)TB * 1024];      // layer1 output
__device__ float g_feats[(size_t)TB * KK];     // emissions
__device__ float g_hbuf[2 * 2 * BB * HH];      // [parity][dir][b][j]
__device__ float g_logz[BB];

// grid barrier state
__device__ unsigned g_cnt = 0;
__device__ unsigned g_gen = 0;

// ---------------- helpers ----------------
__device__ __forceinline__ void ffma2(ull &d, ull a, ull b) {
    asm("fma.rn.f32x2 %0, %1, %2, %0;" : "+l"(d) : "l"(a), "l"(b));
}
__device__ __forceinline__ float2 unpack2(ull v) {
    float2 r;
    asm("mov.b64 {%0, %1}, %2;" : "=f"(r.x), "=f"(r.y) : "l"(v));
    return r;
}
__device__ __forceinline__ ull pk2(float lo, float hi) {
    ull v;
    asm("mov.b64 %0, {%1,%2};" : "=l"(v) : "f"(lo), "f"(hi));
    return v;
}
__device__ __forceinline__ float sigmoidf_(float x) { return 1.0f / (1.0f + expf(-x)); }

__device__ __forceinline__ uint32_t s2u(const void* p) {
    uint32_t a;
    asm("{ .reg .u64 t; cvta.to.shared.u64 t, %1; cvt.u32.u64 %0, t; }" : "=r"(a) : "l"(p));
    return a;
}
__device__ __forceinline__ void mwait(uint32_t mbar, uint32_t phase) {
    asm volatile(
        "{\n\t.reg .pred P;\n"
        "W%=:\n\t"
        "mbarrier.try_wait.parity.acquire.cta.shared::cta.b64 P, [%0], %1, 0x989680;\n\t"
        "@P bra D%=;\n\t"
        "bra W%=;\n"
        "D%=:\n\t}"
        :: "r"(mbar), "r"(phase) : "memory");
}

__device__ __forceinline__ void grid_barrier() {
    __syncthreads();
    if (threadIdx.x == 0) {
        __threadfence();
        unsigned my = *((volatile unsigned*)&g_gen);
        if (atomicAdd(&g_cnt, 1u) == gridDim.x - 1) {
            g_cnt = 0;
            __threadfence();
            *((volatile unsigned*)&g_gen) = my + 1;
        } else {
            while (*((volatile unsigned*)&g_gen) == my) { }
        }
        __threadfence();
    }
    __syncthreads();
}

// ---------------- SGEMM: C[16384][4096] = A[M][KD]*Bw[4096][KD]^T + bias ------
// 128x128 tile, 512 threads, f32x2. Loaders pack k-pairs in registers (STS.64,
// conflict-free 4*kp banking). Bs consumer XOR-swizzled -> conflict-free LDS.128.
// Thread (tn=tid&15, tm=tid>>4): outputs m = m0+tm*4+i (i<4), n = n0+tn*8+j (j<8).
template<int KD, bool GATHER>
__global__ __launch_bounds__(512) void k_gemm(
    const float* __restrict__ A, const int* __restrict__ tok,
    const float* __restrict__ Bw, const float* __restrict__ bias,
    float* __restrict__ C)
{
    __shared__ ull As[8 * 130];
    __shared__ ull Bs[8 * 130];
    int tid = threadIdx.x;
    int n0 = blockIdx.x * 128, m0 = blockIdx.y * 128;
    int tn = tid & 15, tm = tid >> 4;

    // loader role: kp = k-pair (0..7), rows rr + 64*i
    int kp = tid & 7, rr = tid >> 3;   // rr 0..63
    const float* aro[2];
    const float* bro[2];
    int sA[2], sB[2];
#pragma unroll
    for (int i = 0; i < 2; i++) {
        int r = rr + 64 * i;
        aro[i] = (GATHER ? A + (size_t)tok[m0 + r] * KD
                         : A + (size_t)(m0 + r) * KD) + 2 * kp;
        bro[i] = Bw + (size_t)(n0 + r) * KD + 2 * kp;
        sA[i] = kp * 130 + r;
        int t8 = r >> 3, j = (r >> 1) & 3, sw = (r >> 4) & 3;
        sB[i] = kp * 130 + (t8 * 4 + (j ^ sw)) * 2 + (r & 1);
    }

    float bb[8];
#pragma unroll
    for (int j = 0; j < 8; j++) bb[j] = bias[n0 + tn * 8 + j];

    ull acc[4][8];
#pragma unroll
    for (int i = 0; i < 4; i++)
#pragma unroll
        for (int j = 0; j < 8; j++) acc[i][j] = 0ull;

    float2 pa[2], pb[2];
#pragma unroll
    for (int i = 0; i < 2; i++) { pa[i] = *(const float2*)aro[i]; pb[i] = *(const float2*)bro[i]; }

    int swc = (tn >> 1) & 3;

    for (int k0 = 0; k0 < KD; k0 += 16) {
#pragma unroll
        for (int i = 0; i < 2; i++) {
            As[sA[i]] = pk2(pa[i].x, pa[i].y);
            Bs[sB[i]] = pk2(pb[i].x, pb[i].y);
        }
        __syncthreads();
        if (k0 + 16 < KD) {
#pragma unroll
            for (int i = 0; i < 2; i++) {
                pa[i] = *(const float2*)(aro[i] + k0 + 16);
                pb[i] = *(const float2*)(bro[i] + k0 + 16);
            }
        }
#pragma unroll
        for (int k2 = 0; k2 < 8; k2++) {
            ull a2[4], b2[8];
            {
                ulonglong2 v0 = *(const ulonglong2*)&As[k2 * 130 + tm * 4];
                ulonglong2 v1 = *(const ulonglong2*)&As[k2 * 130 + tm * 4 + 2];
                a2[0] = v0.x; a2[1] = v0.y; a2[2] = v1.x; a2[3] = v1.y;
            }
#pragma unroll
            for (int j = 0; j < 4; j++) {
                ulonglong2 v = *(const ulonglong2*)&Bs[k2 * 130 + (tn * 4 + (j ^ swc)) * 2];
                b2[2 * j] = v.x; b2[2 * j + 1] = v.y;
            }
#pragma unroll
            for (int i = 0; i < 4; i++)
#pragma unroll
                for (int j = 0; j < 8; j++)
                    ffma2(acc[i][j], a2[i], b2[j]);
        }
        __syncthreads();
    }
#pragma unroll
    for (int i = 0; i < 4; i++) {
        int m = m0 + tm * 4 + i;
        float o[8];
#pragma unroll
        for (int j = 0; j < 8; j++) {
            float2 u = unpack2(acc[i][j]);
            o[j] = u.x + u.y + bb[j];
        }
        *(float4*)&C[(size_t)m * NG + n0 + tn * 8]     = make_float4(o[0], o[1], o[2], o[3]);
        *(float4*)&C[(size_t)m * NG + n0 + tn * 8 + 4] = make_float4(o[4], o[5], o[6], o[7]);
    }
}

// ---------------- persistent BiLSTM layer kernel ----------------
// grid = 128 CTAs (1/SM), 256 threads. CTA c: dir = c>>6, owns h-cols j0..j0+7.
// Weights resident in SMEM in two gate-pair planes (conflict-free LDS.128).
// Thread (c4 = tid&7, ks = (tid>>3)&3, rg = tid>>5): rows rg*8..+7, col j0+c4,
// k-quarter ks. Cross-ks reduction via shfl_xor(8) + shfl_xor(16).
__global__ __launch_bounds__(256) void k_lstm(
    const float* __restrict__ xp,   // [TB][4096]: dir*2048 + gt*512 + j (bias incl)
    const float* __restrict__ whh,  // raw [2][2048][512]
    float* __restrict__ hout)       // [TB][1024]: dir*512 + j
{
    extern __shared__ float sm[];
    float* h_s = sm;                                  // 32768 floats (128KB)
    ulonglong2* wA = (ulonglong2*)(sm + 32768);       // gates 0,1: 2048 slots (32KB)
    ulonglong2* wB = wA + 2048;                       // gates 2,3: 2048 slots (32KB)
    ull* mbar = (ull*)(wB + 2048);

    int tid = threadIdx.x, cta = blockIdx.x;
    int dir = cta >> 6, j0 = (cta & 63) * 8;
    int c4 = tid & 7, ks = (tid >> 3) & 3, rg = tid >> 5;

    uint32_t mbar_u = s2u(mbar), hdst_u = s2u(h_s);
    if (tid == 0) asm volatile("mbarrier.init.shared.b64 [%0], 1;" :: "r"(mbar_u));

    // stage weights: plane slot f = (kq*64 + k2)*8 + c4 holds ulonglong2 of
    // (gate0,gate1) [plane A] or (gate2,gate3) [plane B] k-pairs.
    const float* W = whh + (size_t)dir * 2048 * 512;
    for (int f = tid; f < 2048; f += 256) {
        int fc = f & 7, k2 = (f >> 3) & 63, kq = f >> 9;
        int k = kq * 128 + k2 * 2;
        int jc = j0 + fc;
        const float* w0 = W + (size_t)jc * 512 + k;            // gate 0 row jc
        ull a0 = pk2(w0[0],                 w0[1]);
        ull a1 = pk2(w0[512 * 512],         w0[512 * 512 + 1]);
        ull b0 = pk2(w0[1024 * 512],        w0[1024 * 512 + 1]);
        ull b1 = pk2(w0[1536 * 512],        w0[1536 * 512 + 1]);
        ulonglong2 va; va.x = a0; va.y = a1;
        ulonglong2 vb; vb.x = b0; vb.y = b1;
        wA[f] = va;
        wB[f] = vb;
    }
    __syncthreads();

    const ulonglong2* wAp = wA + ks * 512 + c4;
    const ulonglong2* wBp = wB + ks * 512 + c4;
    const float* hb = h_s + (rg * 8) * 512 + ks * 128;

    float creg[8];
#pragma unroll
    for (int i = 0; i < 8; i++) creg[i] = 0.0f;

    for (int s = 0; s < TT; s++) {
        int t = dir ? (TT - 1 - s) : s;
        int par = s & 1;

        // kick off h copy for this step (producer writes fenced by grid barrier)
        if (s > 0 && tid == 0) {
            const float* src = g_hbuf + (size_t)(par * 2 + dir) * BB * HH;
            asm volatile("mbarrier.arrive.expect_tx.shared.b64 _, [%0], %1;"
                         :: "r"(mbar_u), "r"((uint32_t)HBYTES));
            asm volatile("cp.async.bulk.shared::cta.global.mbarrier::complete_tx::bytes [%0], [%1], %2, [%3];"
                         :: "r"(hdst_u), "l"(src), "r"((uint32_t)HBYTES), "r"(mbar_u) : "memory");
        }

        // prefetch xp while copy is in flight (only ks==0 threads use it)
        float xpre[8][4];
        if (ks == 0) {
#pragma unroll
            for (int i = 0; i < 8; i++) {
                int b = rg * 8 + i;
                const float* xr = xp + (size_t)(t * BB + b) * NG + dir * 2048 + j0 + c4;
                xpre[i][0] = xr[0];
                xpre[i][1] = xr[512];
                xpre[i][2] = xr[1024];
                xpre[i][3] = xr[1536];
            }
        }

        float af[8][4];
        if (s > 0) {
            mwait(mbar_u, (s - 1) & 1);

            ull acc[8][4];
#pragma unroll
            for (int i = 0; i < 8; i++)
#pragma unroll
                for (int g = 0; g < 4; g++) acc[i][g] = 0ull;

#pragma unroll 2
            for (int q = 0; q < 64; q += 2) {
                ulonglong2 wa0 = wAp[q * 8];
                ulonglong2 wb0 = wBp[q * 8];
                ulonglong2 wa1 = wAp[(q + 1) * 8];
                ulonglong2 wb1 = wBp[(q + 1) * 8];
#pragma unroll
                for (int i = 0; i < 8; i++) {
                    ulonglong2 h2 = *(const ulonglong2*)(hb + i * 512 + q * 2);
                    ffma2(acc[i][0], h2.x, wa0.x);
                    ffma2(acc[i][1], h2.x, wa0.y);
                    ffma2(acc[i][2], h2.x, wb0.x);
                    ffma2(acc[i][3], h2.x, wb0.y);
                    ffma2(acc[i][0], h2.y, wa1.x);
                    ffma2(acc[i][1], h2.y, wa1.y);
                    ffma2(acc[i][2], h2.y, wb1.x);
                    ffma2(acc[i][3], h2.y, wb1.y);
                }
            }
            // cross-ks reduction: lanes (ks in bits 3,4 of lane id)
#pragma unroll
            for (int i = 0; i < 8; i++)
#pragma unroll
                for (int g = 0; g < 4; g++) {
                    float2 u = unpack2(acc[i][g]);
                    float v = u.x + u.y;
                    v += __shfl_xor_sync(0xffffffffu, v, 8);
                    v += __shfl_xor_sync(0xffffffffu, v, 16);
                    af[i][g] = v;
                }
        }

        if (ks == 0) {
#pragma unroll
            for (int i = 0; i < 8; i++) {
                int b = rg * 8 + i;
                float p0 = xpre[i][0], p1 = xpre[i][1], p2 = xpre[i][2], p3 = xpre[i][3];
                if (s > 0) { p0 += af[i][0]; p1 += af[i][1]; p2 += af[i][2]; p3 += af[i][3]; }
                float ig = sigmoidf_(p0);
                float fg = sigmoidf_(p1);
                float gg = tanhf(p2);
                float og = sigmoidf_(p3);
                float c = fg * creg[i] + ig * gg;
                creg[i] = c;
                float h = og * tanhf(c);
                int j = j0 + c4;
                g_hbuf[(size_t)(((par ^ 1) * 2 + dir) * BB + b) * HH + j] = h;
                hout[(size_t)(t * BB + b) * 1024 + dir * 512 + j] = h;
            }
        }
        grid_barrier();
    }
}

// ---------------- emission features: feats = h1 @ lin_w^T + lin_b ----------------
__global__ __launch_bounds__(256) void k_feats(
    const float* __restrict__ h1, const float* __restrict__ lin_w,
    const float* __restrict__ lin_b, float* __restrict__ feats)
{
    extern __shared__ float s[];  // [1024][32] transposed lin_w
    int tid = threadIdx.x;
    for (int i = tid; i < 32 * 1024; i += 256) {
        int c = i & 31, k = i >> 5;
        s[k * 32 + c] = lin_w[c * 1024 + k];
    }
    float bias = lin_b[tid & 31];
    __syncthreads();
    int warp = tid >> 5, lane = tid & 31;
    int rows = TB / gridDim.x;
    int r0 = blockIdx.x * rows;
    for (int r = r0 + warp; r < r0 + rows; r += 8) {
        const float* x = h1 + (size_t)r * 1024;
        float acc = 0.0f;
        for (int k0 = 0; k0 < 1024; k0 += 32) {
            float xv = x[k0 + lane];
#pragma unroll
            for (int kk = 0; kk < 32; kk++) {
                float xs = __shfl_sync(0xffffffffu, xv, kk);
                acc += xs * s[(k0 + kk) * 32 + lane];
            }
        }
        feats[(size_t)r * 32 + lane] = acc + bias;
    }
}

// ---------------- CRF forward (one warp per batch, lane = tag) ----------------
__global__ __launch_bounds__(32) void k_crf(
    const float* __restrict__ feats, const float* __restrict__ trans,
    const int* __restrict__ tokens, float* __restrict__ logz)
{
    __shared__ float s_tr[32 * 33];
    int lane = threadIdx.x;
    for (int i = lane; i < 1024; i += 32)
        s_tr[(i >> 5) * 33 + (i & 31)] = trans[i];
    __syncwarp();
    int b = blockIdx.x;

    float alpha = (lane == STARTT) ? 0.0f : NEGV;
    for (int t = 0; t < TT; t++) {
        float emit = feats[(size_t)(t * BB + b) * 32 + lane];
        int m = tokens[t * BB + b] > 0;
        float v[32];
        float mx = -3.4e38f;
#pragma unroll
        for (int k = 0; k < 32; k++) {
            float ak = __shfl_sync(0xffffffffu, alpha, k);
            v[k] = ak + s_tr[lane * 33 + k];
            mx = fmaxf(mx, v[k]);
        }
        float ssum = 0.0f;
#pragma unroll
        for (int k = 0; k < 32; k++) ssum += __expf(v[k] - mx);
        float nv = mx + __logf(ssum) + emit;
        alpha = m ? nv : alpha;
    }
    float val = alpha + s_tr[ENDT * 33 + lane];
    float mx = val;
#pragma unroll
    for (int o = 16; o; o >>= 1) mx = fmaxf(mx, __shfl_xor_sync(0xffffffffu, mx, o));
    float ss = __expf(val - mx);
#pragma unroll
    for (int o = 16; o; o >>= 1) ss += __shfl_xor_sync(0xffffffffu, ss, o);
    if (lane == 0) logz[b] = mx + __logf(ss);
}

// ---------------- gold score + final reduction ----------------
__global__ void k_final(
    const int* __restrict__ tags, const int* __restrict__ tokens,
    const float* __restrict__ trans, const float* __restrict__ feats,
    const float* __restrict__ logz, const int* __restrict__ lengths,
    float* __restrict__ out)
{
    __shared__ float red[BB];
    int b = threadIdx.x;
    float gold = 0.0f;
    int prev = STARTT;
    for (int t = 0; t < TT; t++) {
        int cur = tags[t * BB + b];
        float m = tokens[t * BB + b] > 0 ? 1.0f : 0.0f;
        gold += m * (trans[cur * 32 + prev] + feats[(size_t)(t * BB + b) * 32 + cur]);
        prev = cur;
    }
    gold += trans[ENDT * 32 + prev];
    red[b] = (logz[b] - gold) / (float)lengths[b];
    __syncthreads();
    if (b == 0) {
        float s = 0.0f;
        for (int i = 0; i < BB; i++) s += red[i];
        out[0] = s;
    }
}

// ---------------- launch ----------------
extern "C" void kernel_launch(void* const* d_in, const int* in_sizes, int n_in,
                              void* d_out, int out_size)
{
    const int*   tokens = (const int*)d_in[0];
    const int*   tags   = (const int*)d_in[1];
    const int*   lens   = (const int*)d_in[2];
    const float* embed  = (const float*)d_in[3];
    const float* wih0   = (const float*)d_in[4];
    const float* whh0   = (const float*)d_in[5];
    const float* b0     = (const float*)d_in[6];
    const float* wih1   = (const float*)d_in[7];
    const float* whh1   = (const float*)d_in[8];
    const float* b1     = (const float*)d_in[9];
    const float* lin_w  = (const float*)d_in[10];
    const float* lin_b  = (const float*)d_in[11];
    const float* trans  = (const float*)d_in[12];
    float* out = (float*)d_out;

    void *p;
    cudaGetSymbolAddress(&p, g_xp);    float* xp    = (float*)p;
    cudaGetSymbolAddress(&p, g_h0);    float* h0    = (float*)p;
    cudaGetSymbolAddress(&p, g_h1);    float* h1    = (float*)p;
    cudaGetSymbolAddress(&p, g_feats); float* feats = (float*)p;
    cudaGetSymbolAddress(&p, g_logz);  float* logz  = (float*)p;

    const int LSTM_SMEM = 32768 * 4 + 2 * 2048 * 16 + 16;  // 196624 B
    cudaFuncSetAttribute(k_lstm, cudaFuncAttributeMaxDynamicSharedMemorySize, LSTM_SMEM);
    cudaFuncSetAttribute(k_feats, cudaFuncAttributeMaxDynamicSharedMemorySize, 131072);

    dim3 gg(NG / 128, TB / 128);   // (32, 128)

    // layer 0
    k_gemm<EE, true><<<gg, 512>>>(embed, tokens, wih0, b0, xp);
    k_lstm<<<128, 256, LSTM_SMEM>>>(xp, whh0, h0);

    // layer 1
    k_gemm<1024, false><<<gg, 512>>>(h0, tokens, wih1, b1, xp);
    k_lstm<<<128, 256, LSTM_SMEM>>>(xp, whh1, h1);

    // emissions
    k_feats<<<128, 256, 131072>>>(h1, lin_w, lin_b, feats);

    // CRF partition function
    k_crf<<<BB, 32>>>(feats, trans, tokens, logz);

    // gold + loss
    k_final<<<1, BB>>>(tags, tokens, trans, feats, logz, lens, out);
}

// round 4
// speedup vs baseline: 2.4699x; 1.0217x over previous
#include <cuda_runtime.h>
#include <cuda_bf16.h>
#include <cstdint>

typedef unsigned long long ull;

// ---------------- problem constants ----------------
#define TT   256
#define BB   64
#define EE   512
#define HH   512
#define KK   32
#define TB   (TT*BB)        // 16384
#define NG   4096           // 2 dirs * 4H gate columns
#define STARTT 30
#define ENDT   31
#define NEGV  (-100000.0f)

#define HBYTES  (BB*HH*4)   // 131072
#define CHUNKB  16384       // 8 rows * 512 * 4B

// ---------------- device scratch (static, no cudaMalloc) ----------------
__device__ float g_xp[(size_t)TB * NG];        // reused by both layers
__device__ float g_h0[(size_t)TB * 1024];      // layer0 output (fwd|bwd)
__device__ float g_h1[(size_t)TB * 1024];      // layer1 output
__device__ float g_feats[(size_t)TB * KK];     // emissions
__device__ float g_hbuf[2 * 2 * BB * HH];      // [parity][dir][b][j]
__device__ float g_logz[BB];

// per-direction grid barrier state
__device__ unsigned g_cnt2[2] = {0, 0};
__device__ unsigned g_gen2[2] = {0, 0};

// ---------------- helpers ----------------
__device__ __forceinline__ void ffma2(ull &d, ull a, ull b) {
    asm("fma.rn.f32x2 %0, %1, %2, %0;" : "+l"(d) : "l"(a), "l"(b));
}
__device__ __forceinline__ float2 unpack2(ull v) {
    float2 r;
    asm("mov.b64 {%0, %1}, %2;" : "=f"(r.x), "=f"(r.y) : "l"(v));
    return r;
}
__device__ __forceinline__ ull pk2(float lo, float hi) {
    ull v;
    asm("mov.b64 %0, {%1,%2};" : "=l"(v) : "f"(lo), "f"(hi));
    return v;
}
__device__ __forceinline__ float sigmoidf_(float x) { return 1.0f / (1.0f + expf(-x)); }

__device__ __forceinline__ uint32_t s2u(const void* p) {
    uint32_t a;
    asm("{ .reg .u64 t; cvta.to.shared.u64 t, %1; cvt.u32.u64 %0, t; }" : "=r"(a) : "l"(p));
    return a;
}
__device__ __forceinline__ void mwait(uint32_t mbar, uint32_t phase) {
    asm volatile(
        "{\n\t.reg .pred P;\n"
        "W%=:\n\t"
        "mbarrier.try_wait.parity.acquire.cta.shared::cta.b64 P, [%0], %1, 0x989680;\n\t"
        "@P bra D%=;\n\t"
        "bra W%=;\n"
        "D%=:\n\t}"
        :: "r"(mbar), "r"(phase) : "memory");
}

__device__ __forceinline__ void grid_barrier(int dir) {
    __syncthreads();
    if (threadIdx.x == 0) {
        __threadfence();
        unsigned my = *((volatile unsigned*)&g_gen2[dir]);
        if (atomicAdd(&g_cnt2[dir], 1u) == 63u) {
            g_cnt2[dir] = 0;
            __threadfence();
            *((volatile unsigned*)&g_gen2[dir]) = my + 1;
        } else {
            while (*((volatile unsigned*)&g_gen2[dir]) == my) { }
        }
        __threadfence();
    }
    __syncthreads();
}

// ---------------- SGEMM: C[16384][4096] = A[M][KD]*Bw[4096][KD]^T + bias ------
// 128x128 tile, 512 threads, f32x2. Loaders pack k-pairs in registers (STS.64,
// conflict-free 4*kp banking). Bs consumer XOR-swizzled -> conflict-free LDS.128.
template<int KD, bool GATHER>
__global__ __launch_bounds__(512) void k_gemm(
    const float* __restrict__ A, const int* __restrict__ tok,
    const float* __restrict__ Bw, const float* __restrict__ bias,
    float* __restrict__ C)
{
    __shared__ ull As[8 * 130];
    __shared__ ull Bs[8 * 130];
    int tid = threadIdx.x;
    int n0 = blockIdx.x * 128, m0 = blockIdx.y * 128;
    int tn = tid & 15, tm = tid >> 4;

    int kp = tid & 7, rr = tid >> 3;   // rr 0..63
    const float* aro[2];
    const float* bro[2];
    int sA[2], sB[2];
#pragma unroll
    for (int i = 0; i < 2; i++) {
        int r = rr + 64 * i;
        aro[i] = (GATHER ? A + (size_t)tok[m0 + r] * KD
                         : A + (size_t)(m0 + r) * KD) + 2 * kp;
        bro[i] = Bw + (size_t)(n0 + r) * KD + 2 * kp;
        sA[i] = kp * 130 + r;
        int t8 = r >> 3, j = (r >> 1) & 3, sw = (r >> 4) & 3;
        sB[i] = kp * 130 + (t8 * 4 + (j ^ sw)) * 2 + (r & 1);
    }

    float bb[8];
#pragma unroll
    for (int j = 0; j < 8; j++) bb[j] = bias[n0 + tn * 8 + j];

    ull acc[4][8];
#pragma unroll
    for (int i = 0; i < 4; i++)
#pragma unroll
        for (int j = 0; j < 8; j++) acc[i][j] = 0ull;

    float2 pa[2], pb[2];
#pragma unroll
    for (int i = 0; i < 2; i++) { pa[i] = *(const float2*)aro[i]; pb[i] = *(const float2*)bro[i]; }

    int swc = (tn >> 1) & 3;

    for (int k0 = 0; k0 < KD; k0 += 16) {
#pragma unroll
        for (int i = 0; i < 2; i++) {
            As[sA[i]] = pk2(pa[i].x, pa[i].y);
            Bs[sB[i]] = pk2(pb[i].x, pb[i].y);
        }
        __syncthreads();
        if (k0 + 16 < KD) {
#pragma unroll
            for (int i = 0; i < 2; i++) {
                pa[i] = *(const float2*)(aro[i] + k0 + 16);
                pb[i] = *(const float2*)(bro[i] + k0 + 16);
            }
        }
#pragma unroll
        for (int k2 = 0; k2 < 8; k2++) {
            ull a2[4], b2[8];
            {
                ulonglong2 v0 = *(const ulonglong2*)&As[k2 * 130 + tm * 4];
                ulonglong2 v1 = *(const ulonglong2*)&As[k2 * 130 + tm * 4 + 2];
                a2[0] = v0.x; a2[1] = v0.y; a2[2] = v1.x; a2[3] = v1.y;
            }
#pragma unroll
            for (int j = 0; j < 4; j++) {
                ulonglong2 v = *(const ulonglong2*)&Bs[k2 * 130 + (tn * 4 + (j ^ swc)) * 2];
                b2[2 * j] = v.x; b2[2 * j + 1] = v.y;
            }
#pragma unroll
            for (int i = 0; i < 4; i++)
#pragma unroll
                for (int j = 0; j < 8; j++)
                    ffma2(acc[i][j], a2[i], b2[j]);
        }
        __syncthreads();
    }
#pragma unroll
    for (int i = 0; i < 4; i++) {
        int m = m0 + tm * 4 + i;
        float o[8];
#pragma unroll
        for (int j = 0; j < 8; j++) {
            float2 u = unpack2(acc[i][j]);
            o[j] = u.x + u.y + bb[j];
        }
        *(float4*)&C[(size_t)m * NG + n0 + tn * 8]     = make_float4(o[0], o[1], o[2], o[3]);
        *(float4*)&C[(size_t)m * NG + n0 + tn * 8 + 4] = make_float4(o[4], o[5], o[6], o[7]);
    }
}

// ---------------- persistent BiLSTM layer kernel ----------------
// grid = 128 CTAs (1/SM), 256 threads. CTA c: dir = c>>6, owns h-cols j0..j0+7.
// Weights resident in SMEM in two gate-pair planes (conflict-free LDS.128).
// h delivered per-step in 8 row-chunks (16KB each) with 8 mbarriers; warp rg
// waits only on chunk rg. Cross-ks reduction via shfl_xor(8) + shfl_xor(16).
__global__ __launch_bounds__(256) void k_lstm(
    const float* __restrict__ xp,   // [TB][4096]: dir*2048 + gt*512 + j (bias incl)
    const float* __restrict__ whh,  // raw [2][2048][512]
    float* __restrict__ hout)       // [TB][1024]: dir*512 + j
{
    extern __shared__ float sm[];
    float* h_s = sm;                                  // 32768 floats (128KB)
    ulonglong2* wA = (ulonglong2*)(sm + 32768);       // gates 0,1: 2048 slots (32KB)
    ulonglong2* wB = wA + 2048;                       // gates 2,3: 2048 slots (32KB)
    ull* mbar = (ull*)(wB + 2048);                    // 8 mbarriers

    int tid = threadIdx.x, cta = blockIdx.x;
    int dir = cta >> 6, j0 = (cta & 63) * 8;
    int c4 = tid & 7, ks = (tid >> 3) & 3, rg = tid >> 5;

    uint32_t mbar_u = s2u(mbar), hdst_u = s2u(h_s);
    if (tid < 8)
        asm volatile("mbarrier.init.shared.b64 [%0], 1;" :: "r"(mbar_u + tid * 8));

    // stage weights: plane slot f = (kq*64 + k2)*8 + c4 holds ulonglong2 of
    // (gate0,gate1) [plane A] or (gate2,gate3) [plane B] k-pairs.
    const float* W = whh + (size_t)dir * 2048 * 512;
    for (int f = tid; f < 2048; f += 256) {
        int fc = f & 7, k2 = (f >> 3) & 63, kq = f >> 9;
        int k = kq * 128 + k2 * 2;
        int jc = j0 + fc;
        const float* w0 = W + (size_t)jc * 512 + k;            // gate 0 row jc
        ull a0 = pk2(w0[0],                 w0[1]);
        ull a1 = pk2(w0[512 * 512],         w0[512 * 512 + 1]);
        ull b0 = pk2(w0[1024 * 512],        w0[1024 * 512 + 1]);
        ull b1 = pk2(w0[1536 * 512],        w0[1536 * 512 + 1]);
        ulonglong2 va; va.x = a0; va.y = a1;
        ulonglong2 vb; vb.x = b0; vb.y = b1;
        wA[f] = va;
        wB[f] = vb;
    }
    __syncthreads();

    const ulonglong2* wAp = wA + ks * 512 + c4;
    const ulonglong2* wBp = wB + ks * 512 + c4;
    const float* hb = h_s + (rg * 8) * 512 + ks * 128;

    float creg[8];
#pragma unroll
    for (int i = 0; i < 8; i++) creg[i] = 0.0f;

    for (int s = 0; s < TT; s++) {
        int t = dir ? (TT - 1 - s) : s;
        int par = s & 1;

        // kick off 8 independent row-chunk copies (producer writes fenced by
        // the per-direction grid barrier at the end of the previous step)
        if (s > 0 && tid < 8) {
            const float* src = g_hbuf + (size_t)(par * 2 + dir) * BB * HH + tid * 4096;
            uint32_t mb = mbar_u + tid * 8;
            asm volatile("mbarrier.arrive.expect_tx.shared.b64 _, [%0], %1;"
                         :: "r"(mb), "r"((uint32_t)CHUNKB));
            asm volatile("cp.async.bulk.shared::cta.global.mbarrier::complete_tx::bytes [%0], [%1], %2, [%3];"
                         :: "r"(hdst_u + (uint32_t)tid * CHUNKB), "l"(src),
                            "r"((uint32_t)CHUNKB), "r"(mb) : "memory");
        }

        // prefetch xp while copies are in flight (only ks==0 threads use it)
        float xpre[8][4];
        if (ks == 0) {
#pragma unroll
            for (int i = 0; i < 8; i++) {
                int b = rg * 8 + i;
                const float* xr = xp + (size_t)(t * BB + b) * NG + dir * 2048 + j0 + c4;
                xpre[i][0] = xr[0];
                xpre[i][1] = xr[512];
                xpre[i][2] = xr[1024];
                xpre[i][3] = xr[1536];
            }
        }

        float af[8][4];
        if (s > 0) {
            // wait only for THIS warp's row chunk
            mwait(mbar_u + rg * 8, (s - 1) & 1);

            ull acc[8][4];
#pragma unroll
            for (int i = 0; i < 8; i++)
#pragma unroll
                for (int g = 0; g < 4; g++) acc[i][g] = 0ull;

#pragma unroll 4
            for (int q = 0; q < 64; q += 2) {
                ulonglong2 wa0 = wAp[q * 8];
                ulonglong2 wb0 = wBp[q * 8];
                ulonglong2 wa1 = wAp[(q + 1) * 8];
                ulonglong2 wb1 = wBp[(q + 1) * 8];
#pragma unroll
                for (int i = 0; i < 8; i++) {
                    ulonglong2 h2 = *(const ulonglong2*)(hb + i * 512 + q * 2);
                    ffma2(acc[i][0], h2.x, wa0.x);
                    ffma2(acc[i][1], h2.x, wa0.y);
                    ffma2(acc[i][2], h2.x, wb0.x);
                    ffma2(acc[i][3], h2.x, wb0.y);
                    ffma2(acc[i][0], h2.y, wa1.x);
                    ffma2(acc[i][1], h2.y, wa1.y);
                    ffma2(acc[i][2], h2.y, wb1.x);
                    ffma2(acc[i][3], h2.y, wb1.y);
                }
            }
            // cross-ks reduction: lanes (ks in bits 3,4 of lane id)
#pragma unroll
            for (int i = 0; i < 8; i++)
#pragma unroll
                for (int g = 0; g < 4; g++) {
                    float2 u = unpack2(acc[i][g]);
                    float v = u.x + u.y;
                    v += __shfl_xor_sync(0xffffffffu, v, 8);
                    v += __shfl_xor_sync(0xffffffffu, v, 16);
                    af[i][g] = v;
                }
        }

        if (ks == 0) {
#pragma unroll
            for (int i = 0; i < 8; i++) {
                int b = rg * 8 + i;
                float p0 = xpre[i][0], p1 = xpre[i][1], p2 = xpre[i][2], p3 = xpre[i][3];
                if (s > 0) { p0 += af[i][0]; p1 += af[i][1]; p2 += af[i][2]; p3 += af[i][3]; }
                float ig = sigmoidf_(p0);
                float fg = sigmoidf_(p1);
                float gg = tanhf(p2);
                float og = sigmoidf_(p3);
                float c = fg * creg[i] + ig * gg;
                creg[i] = c;
                float h = og * tanhf(c);
                int j = j0 + c4;
                g_hbuf[(size_t)(((par ^ 1) * 2 + dir) * BB + b) * HH + j] = h;
                hout[(size_t)(t * BB + b) * 1024 + dir * 512 + j] = h;
            }
        }
        grid_barrier(dir);
    }
}

// ---------------- emission features: feats = h1 @ lin_w^T + lin_b ----------------
__global__ __launch_bounds__(256) void k_feats(
    const float* __restrict__ h1, const float* __restrict__ lin_w,
    const float* __restrict__ lin_b, float* __restrict__ feats)
{
    extern __shared__ float s[];  // [1024][32] transposed lin_w
    int tid = threadIdx.x;
    for (int i = tid; i < 32 * 1024; i += 256) {
        int c = i & 31, k = i >> 5;
        s[k * 32 + c] = lin_w[c * 1024 + k];
    }
    float bias = lin_b[tid & 31];
    __syncthreads();
    int warp = tid >> 5, lane = tid & 31;
    int rows = TB / gridDim.x;
    int r0 = blockIdx.x * rows;
    for (int r = r0 + warp; r < r0 + rows; r += 8) {
        const float* x = h1 + (size_t)r * 1024;
        float acc = 0.0f;
        for (int k0 = 0; k0 < 1024; k0 += 32) {
            float xv = x[k0 + lane];
#pragma unroll
            for (int kk = 0; kk < 32; kk++) {
                float xs = __shfl_sync(0xffffffffu, xv, kk);
                acc += xs * s[(k0 + kk) * 32 + lane];
            }
        }
        feats[(size_t)r * 32 + lane] = acc + bias;
    }
}

// ---------------- CRF forward (one warp per batch, lane = tag) ----------------
__global__ __launch_bounds__(32) void k_crf(
    const float* __restrict__ feats, const float* __restrict__ trans,
    const int* __restrict__ tokens, float* __restrict__ logz)
{
    __shared__ float s_tr[32 * 33];
    int lane = threadIdx.x;
    for (int i = lane; i < 1024; i += 32)
        s_tr[(i >> 5) * 33 + (i & 31)] = trans[i];
    __syncwarp();
    int b = blockIdx.x;

    float alpha = (lane == STARTT) ? 0.0f : NEGV;
    for (int t = 0; t < TT; t++) {
        float emit = feats[(size_t)(t * BB + b) * 32 + lane];
        int m = tokens[t * BB + b] > 0;
        float v[32];
        float mx = -3.4e38f;
#pragma unroll
        for (int k = 0; k < 32; k++) {
            float ak = __shfl_sync(0xffffffffu, alpha, k);
            v[k] = ak + s_tr[lane * 33 + k];
            mx = fmaxf(mx, v[k]);
        }
        float ssum = 0.0f;
#pragma unroll
        for (int k = 0; k < 32; k++) ssum += __expf(v[k] - mx);
        float nv = mx + __logf(ssum) + emit;
        alpha = m ? nv : alpha;
    }
    float val = alpha + s_tr[ENDT * 33 + lane];
    float mx = val;
#pragma unroll
    for (int o = 16; o; o >>= 1) mx = fmaxf(mx, __shfl_xor_sync(0xffffffffu, mx, o));
    float ss = __expf(val - mx);
#pragma unroll
    for (int o = 16; o; o >>= 1) ss += __shfl_xor_sync(0xffffffffu, ss, o);
    if (lane == 0) logz[b] = mx + __logf(ss);
}

// ---------------- gold score + final reduction ----------------
__global__ void k_final(
    const int* __restrict__ tags, const int* __restrict__ tokens,
    const float* __restrict__ trans, const float* __restrict__ feats,
    const float* __restrict__ logz, const int* __restrict__ lengths,
    float* __restrict__ out)
{
    __shared__ float red[BB];
    int b = threadIdx.x;
    float gold = 0.0f;
    int prev = STARTT;
    for (int t = 0; t < TT; t++) {
        int cur = tags[t * BB + b];
        float m = tokens[t * BB + b] > 0 ? 1.0f : 0.0f;
        gold += m * (trans[cur * 32 + prev] + feats[(size_t)(t * BB + b) * 32 + cur]);
        prev = cur;
    }
    gold += trans[ENDT * 32 + prev];
    red[b] = (logz[b] - gold) / (float)lengths[b];
    __syncthreads();
    if (b == 0) {
        float s = 0.0f;
        for (int i = 0; i < BB; i++) s += red[i];
        out[0] = s;
    }
}

// ---------------- launch ----------------
extern "C" void kernel_launch(void* const* d_in, const int* in_sizes, int n_in,
                              void* d_out, int out_size)
{
    const int*   tokens = (const int*)d_in[0];
    const int*   tags   = (const int*)d_in[1];
    const int*   lens   = (const int*)d_in[2];
    const float* embed  = (const float*)d_in[3];
    const float* wih0   = (const float*)d_in[4];
    const float* whh0   = (const float*)d_in[5];
    const float* b0     = (const float*)d_in[6];
    const float* wih1   = (const float*)d_in[7];
    const float* whh1   = (const float*)d_in[8];
    const float* b1     = (const float*)d_in[9];
    const float* lin_w  = (const float*)d_in[10];
    const float* lin_b  = (const float*)d_in[11];
    const float* trans  = (const float*)d_in[12];
    float* out = (float*)d_out;

    void *p;
    cudaGetSymbolAddress(&p, g_xp);    float* xp    = (float*)p;
    cudaGetSymbolAddress(&p, g_h0);    float* h0    = (float*)p;
    cudaGetSymbolAddress(&p, g_h1);    float* h1    = (float*)p;
    cudaGetSymbolAddress(&p, g_feats); float* feats = (float*)p;
    cudaGetSymbolAddress(&p, g_logz);  float* logz  = (float*)p;

    const int LSTM_SMEM = 32768 * 4 + 2 * 2048 * 16 + 64;  // 196672 B
    cudaFuncSetAttribute(k_lstm, cudaFuncAttributeMaxDynamicSharedMemorySize, LSTM_SMEM);
    cudaFuncSetAttribute(k_feats, cudaFuncAttributeMaxDynamicSharedMemorySize, 131072);

    dim3 gg(NG / 128, TB / 128);   // (32, 128)

    // layer 0
    k_gemm<EE, true><<<gg, 512>>>(embed, tokens, wih0, b0, xp);
    k_lstm<<<128, 256, LSTM_SMEM>>>(xp, whh0, h0);

    // layer 1
    k_gemm<1024, false><<<gg, 512>>>(h0, tokens, wih1, b1, xp);
    k_lstm<<<128, 256, LSTM_SMEM>>>(xp, whh1, h1);

    // emissions
    k_feats<<<128, 256, 131072>>>(h1, lin_w, lin_b, feats);

    // CRF partition function
    k_crf<<<BB, 32>>>(feats, trans, tokens, logz);

    // gold + loss
    k_final<<<1, BB>>>(tags, tokens, trans, feats, logz, lens, out);
}

// round 5
// speedup vs baseline: 2.4944x; 1.0099x over previous
#include <cuda_runtime.h>
#include <cuda_bf16.h>
#include <cstdint>

typedef unsigned long long ull;

// ---------------- problem constants ----------------
#define TT   256
#define BB   64
#define EE   512
#define HH   512
#define KK   32
#define TB   (TT*BB)        // 16384
#define NG   4096           // 2 dirs * 4H gate columns
#define STARTT 30
#define ENDT   31
#define NEGV  (-100000.0f)

#define HBYTES  (BB*HH*4)   // 131072
#define CHUNKB  16384       // 8 rows * 512 * 4B

// ---------------- device scratch (static, no cudaMalloc) ----------------
__device__ float g_xp[(size_t)TB * NG];        // reused by both layers
__device__ float g_h0[(size_t)TB * 1024];      // layer0 output (fwd|bwd)
__device__ float g_h1[(size_t)TB * 1024];      // layer1 output
__device__ float g_feats[(size_t)TB * KK];     // emissions
__device__ float g_hbuf[2 * 2 * BB * HH];      // [parity][dir][b][j]
__device__ float g_logz[BB];

// per-direction grid barrier state
__device__ unsigned g_cnt2[2] = {0, 0};
__device__ unsigned g_gen2[2] = {0, 0};

// ---------------- helpers ----------------
__device__ __forceinline__ void ffma2(ull &d, ull a, ull b) {
    asm("fma.rn.f32x2 %0, %1, %2, %0;" : "+l"(d) : "l"(a), "l"(b));
}
__device__ __forceinline__ float2 unpack2(ull v) {
    float2 r;
    asm("mov.b64 {%0, %1}, %2;" : "=f"(r.x), "=f"(r.y) : "l"(v));
    return r;
}
__device__ __forceinline__ ull pk2(float lo, float hi) {
    ull v;
    asm("mov.b64 %0, {%1,%2};" : "=l"(v) : "f"(lo), "f"(hi));
    return v;
}
__device__ __forceinline__ float sigmoidf_(float x) { return 1.0f / (1.0f + expf(-x)); }

__device__ __forceinline__ uint32_t s2u(const void* p) {
    uint32_t a;
    asm("{ .reg .u64 t; cvta.to.shared.u64 t, %1; cvt.u32.u64 %0, t; }" : "=r"(a) : "l"(p));
    return a;
}
__device__ __forceinline__ void mwait(uint32_t mbar, uint32_t phase) {
    asm volatile(
        "{\n\t.reg .pred P;\n"
        "W%=:\n\t"
        "mbarrier.try_wait.parity.acquire.cta.shared::cta.b64 P, [%0], %1, 0x989680;\n\t"
        "@P bra D%=;\n\t"
        "bra W%=;\n"
        "D%=:\n\t}"
        :: "r"(mbar), "r"(phase) : "memory");
}

__device__ __forceinline__ void grid_barrier(int dir) {
    __syncthreads();
    if (threadIdx.x == 0) {
        __threadfence();
        unsigned my = *((volatile unsigned*)&g_gen2[dir]);
        if (atomicAdd(&g_cnt2[dir], 1u) == 63u) {
            g_cnt2[dir] = 0;
            __threadfence();
            *((volatile unsigned*)&g_gen2[dir]) = my + 1;
        } else {
            while (*((volatile unsigned*)&g_gen2[dir]) == my) { }
        }
        __threadfence();
    }
    __syncthreads();
}

// ---------------- SGEMM: C[16384][4096] = A[M][KD]*Bw[4096][KD]^T + bias ------
// 128x128 tile, 512 threads, f32x2. Loaders pack k-pairs in registers (STS.64,
// conflict-free 4*kp banking). Bs consumer XOR-swizzled -> conflict-free LDS.128.
template<int KD, bool GATHER>
__global__ __launch_bounds__(512) void k_gemm(
    const float* __restrict__ A, const int* __restrict__ tok,
    const float* __restrict__ Bw, const float* __restrict__ bias,
    float* __restrict__ C)
{
    __shared__ ull As[8 * 130];
    __shared__ ull Bs[8 * 130];
    int tid = threadIdx.x;
    int n0 = blockIdx.x * 128, m0 = blockIdx.y * 128;
    int tn = tid & 15, tm = tid >> 4;

    int kp = tid & 7, rr = tid >> 3;   // rr 0..63
    const float* aro[2];
    const float* bro[2];
    int sA[2], sB[2];
#pragma unroll
    for (int i = 0; i < 2; i++) {
        int r = rr + 64 * i;
        aro[i] = (GATHER ? A + (size_t)tok[m0 + r] * KD
                         : A + (size_t)(m0 + r) * KD) + 2 * kp;
        bro[i] = Bw + (size_t)(n0 + r) * KD + 2 * kp;
        sA[i] = kp * 130 + r;
        int t8 = r >> 3, j = (r >> 1) & 3, sw = (r >> 4) & 3;
        sB[i] = kp * 130 + (t8 * 4 + (j ^ sw)) * 2 + (r & 1);
    }

    float bb[8];
#pragma unroll
    for (int j = 0; j < 8; j++) bb[j] = bias[n0 + tn * 8 + j];

    ull acc[4][8];
#pragma unroll
    for (int i = 0; i < 4; i++)
#pragma unroll
        for (int j = 0; j < 8; j++) acc[i][j] = 0ull;

    float2 pa[2], pb[2];
#pragma unroll
    for (int i = 0; i < 2; i++) { pa[i] = *(const float2*)aro[i]; pb[i] = *(const float2*)bro[i]; }

    int swc = (tn >> 1) & 3;

    for (int k0 = 0; k0 < KD; k0 += 16) {
#pragma unroll
        for (int i = 0; i < 2; i++) {
            As[sA[i]] = pk2(pa[i].x, pa[i].y);
            Bs[sB[i]] = pk2(pb[i].x, pb[i].y);
        }
        __syncthreads();
        if (k0 + 16 < KD) {
#pragma unroll
            for (int i = 0; i < 2; i++) {
                pa[i] = *(const float2*)(aro[i] + k0 + 16);
                pb[i] = *(const float2*)(bro[i] + k0 + 16);
            }
        }
#pragma unroll
        for (int k2 = 0; k2 < 8; k2++) {
            ull a2[4], b2[8];
            {
                ulonglong2 v0 = *(const ulonglong2*)&As[k2 * 130 + tm * 4];
                ulonglong2 v1 = *(const ulonglong2*)&As[k2 * 130 + tm * 4 + 2];
                a2[0] = v0.x; a2[1] = v0.y; a2[2] = v1.x; a2[3] = v1.y;
            }
#pragma unroll
            for (int j = 0; j < 4; j++) {
                ulonglong2 v = *(const ulonglong2*)&Bs[k2 * 130 + (tn * 4 + (j ^ swc)) * 2];
                b2[2 * j] = v.x; b2[2 * j + 1] = v.y;
            }
#pragma unroll
            for (int i = 0; i < 4; i++)
#pragma unroll
                for (int j = 0; j < 8; j++)
                    ffma2(acc[i][j], a2[i], b2[j]);
        }
        __syncthreads();
    }
#pragma unroll
    for (int i = 0; i < 4; i++) {
        int m = m0 + tm * 4 + i;
        float o[8];
#pragma unroll
        for (int j = 0; j < 8; j++) {
            float2 u = unpack2(acc[i][j]);
            o[j] = u.x + u.y + bb[j];
        }
        *(float4*)&C[(size_t)m * NG + n0 + tn * 8]     = make_float4(o[0], o[1], o[2], o[3]);
        *(float4*)&C[(size_t)m * NG + n0 + tn * 8 + 4] = make_float4(o[4], o[5], o[6], o[7]);
    }
}

// ---------------- persistent BiLSTM layer kernel ----------------
// grid = 128 CTAs (1/SM), 256 threads. CTA c: dir = c>>6, owns h-cols j0..j0+7.
// Weights resident in SMEM in two gate-pair planes; per-k-quarter ROTATION
// swizzle (q2 = (q + 4*ks) & 63) applied to both weight staging and h reads so
// the 4 ks lanes of each h LDS.128 hit disjoint bank groups (conflict-free).
// h delivered per-step in 8 row-chunks (16KB, 8 mbarriers); warp rg waits only
// on chunk rg. Cross-ks reduction via shfl_xor(8) + shfl_xor(16).
__global__ __launch_bounds__(256) void k_lstm(
    const float* __restrict__ xp,   // [TB][4096]: dir*2048 + gt*512 + j (bias incl)
    const float* __restrict__ whh,  // raw [2][2048][512]
    float* __restrict__ hout)       // [TB][1024]: dir*512 + j
{
    extern __shared__ float sm[];
    float* h_s = sm;                                  // 32768 floats (128KB)
    ulonglong2* wA = (ulonglong2*)(sm + 32768);       // gates 0,1: 2048 slots (32KB)
    ulonglong2* wB = wA + 2048;                       // gates 2,3: 2048 slots (32KB)
    ull* mbar = (ull*)(wB + 2048);                    // 8 mbarriers

    int tid = threadIdx.x, cta = blockIdx.x;
    int dir = cta >> 6, j0 = (cta & 63) * 8;
    int c4 = tid & 7, ks = (tid >> 3) & 3, rg = tid >> 5;

    uint32_t mbar_u = s2u(mbar), hdst_u = s2u(h_s);
    if (tid < 8)
        asm volatile("mbarrier.init.shared.b64 [%0], 1;" :: "r"(mbar_u + tid * 8));

    // stage weights with per-quarter rotation: slot (kq, k2, c4) holds k-pair
    // kq*64 + ((k2 + 4*kq) & 63). Plane A = gates 0,1; plane B = gates 2,3.
    const float* W = whh + (size_t)dir * 2048 * 512;
    for (int f = tid; f < 2048; f += 256) {
        int fc = f & 7, k2 = (f >> 3) & 63, kq = f >> 9;
        int k2r = (k2 + 4 * kq) & 63;
        int k = kq * 128 + k2r * 2;
        int jc = j0 + fc;
        const float* w0 = W + (size_t)jc * 512 + k;            // gate 0 row jc
        ull a0 = pk2(w0[0],                 w0[1]);
        ull a1 = pk2(w0[512 * 512],         w0[512 * 512 + 1]);
        ull b0 = pk2(w0[1024 * 512],        w0[1024 * 512 + 1]);
        ull b1 = pk2(w0[1536 * 512],        w0[1536 * 512 + 1]);
        ulonglong2 va; va.x = a0; va.y = a1;
        ulonglong2 vb; vb.x = b0; vb.y = b1;
        wA[f] = va;
        wB[f] = vb;
    }
    __syncthreads();

    const ulonglong2* wAp = wA + ks * 512 + c4;
    const ulonglong2* wBp = wB + ks * 512 + c4;
    const float* hb = h_s + (rg * 8) * 512 + ks * 128;
    int rot = ks * 4;

    float creg[8];
#pragma unroll
    for (int i = 0; i < 8; i++) creg[i] = 0.0f;

    for (int s = 0; s < TT; s++) {
        int t = dir ? (TT - 1 - s) : s;
        int par = s & 1;

        // kick off 8 independent row-chunk copies (producer writes fenced by
        // the per-direction grid barrier at the end of the previous step)
        if (s > 0 && tid < 8) {
            const float* src = g_hbuf + (size_t)(par * 2 + dir) * BB * HH + tid * 4096;
            uint32_t mb = mbar_u + tid * 8;
            asm volatile("mbarrier.arrive.expect_tx.shared.b64 _, [%0], %1;"
                         :: "r"(mb), "r"((uint32_t)CHUNKB));
            asm volatile("cp.async.bulk.shared::cta.global.mbarrier::complete_tx::bytes [%0], [%1], %2, [%3];"
                         :: "r"(hdst_u + (uint32_t)tid * CHUNKB), "l"(src),
                            "r"((uint32_t)CHUNKB), "r"(mb) : "memory");
        }

        // prefetch xp while copies are in flight (only ks==0 threads use it)
        float xpre[8][4];
        if (ks == 0) {
#pragma unroll
            for (int i = 0; i < 8; i++) {
                int b = rg * 8 + i;
                const float* xr = xp + (size_t)(t * BB + b) * NG + dir * 2048 + j0 + c4;
                xpre[i][0] = xr[0];
                xpre[i][1] = xr[512];
                xpre[i][2] = xr[1024];
                xpre[i][3] = xr[1536];
            }
        }

        float af[8][4];
        if (s > 0) {
            // wait only for THIS warp's row chunk
            mwait(mbar_u + rg * 8, (s - 1) & 1);

            ull acc[8][4];
#pragma unroll
            for (int i = 0; i < 8; i++)
#pragma unroll
                for (int g = 0; g < 4; g++) acc[i][g] = 0ull;

#pragma unroll 4
            for (int q = 0; q < 64; q += 2) {
                int q2 = (q + rot) & 63;     // rotated k-pair (matches staged weights)
                ulonglong2 wa0 = wAp[q * 8];
                ulonglong2 wb0 = wBp[q * 8];
                ulonglong2 wa1 = wAp[(q + 1) * 8];
                ulonglong2 wb1 = wBp[(q + 1) * 8];
#pragma unroll
                for (int i = 0; i < 8; i++) {
                    ulonglong2 h2 = *(const ulonglong2*)(hb + i * 512 + q2 * 2);
                    ffma2(acc[i][0], h2.x, wa0.x);
                    ffma2(acc[i][1], h2.x, wa0.y);
                    ffma2(acc[i][2], h2.x, wb0.x);
                    ffma2(acc[i][3], h2.x, wb0.y);
                    ffma2(acc[i][0], h2.y, wa1.x);
                    ffma2(acc[i][1], h2.y, wa1.y);
                    ffma2(acc[i][2], h2.y, wb1.x);
                    ffma2(acc[i][3], h2.y, wb1.y);
                }
            }
            // cross-ks reduction: lanes (ks in bits 3,4 of lane id)
#pragma unroll
            for (int i = 0; i < 8; i++)
#pragma unroll
                for (int g = 0; g < 4; g++) {
                    float2 u = unpack2(acc[i][g]);
                    float v = u.x + u.y;
                    v += __shfl_xor_sync(0xffffffffu, v, 8);
                    v += __shfl_xor_sync(0xffffffffu, v, 16);
                    af[i][g] = v;
                }
        }

        if (ks == 0) {
#pragma unroll
            for (int i = 0; i < 8; i++) {
                int b = rg * 8 + i;
                float p0 = xpre[i][0], p1 = xpre[i][1], p2 = xpre[i][2], p3 = xpre[i][3];
                if (s > 0) { p0 += af[i][0]; p1 += af[i][1]; p2 += af[i][2]; p3 += af[i][3]; }
                float ig = sigmoidf_(p0);
                float fg = sigmoidf_(p1);
                float gg = tanhf(p2);
                float og = sigmoidf_(p3);
                float c = fg * creg[i] + ig * gg;
                creg[i] = c;
                float h = og * tanhf(c);
                int j = j0 + c4;
                g_hbuf[(size_t)(((par ^ 1) * 2 + dir) * BB + b) * HH + j] = h;
                hout[(size_t)(t * BB + b) * 1024 + dir * 512 + j] = h;
            }
        }
        grid_barrier(dir);
    }
}

// ---------------- emission features: feats = h1 @ lin_w^T + lin_b ----------------
__global__ __launch_bounds__(256) void k_feats(
    const float* __restrict__ h1, const float* __restrict__ lin_w,
    const float* __restrict__ lin_b, float* __restrict__ feats)
{
    extern __shared__ float s[];  // [1024][32] transposed lin_w
    int tid = threadIdx.x;
    for (int i = tid; i < 32 * 1024; i += 256) {
        int c = i & 31, k = i >> 5;
        s[k * 32 + c] = lin_w[c * 1024 + k];
    }
    float bias = lin_b[tid & 31];
    __syncthreads();
    int warp = tid >> 5, lane = tid & 31;
    int rows = TB / gridDim.x;
    int r0 = blockIdx.x * rows;
    for (int r = r0 + warp; r < r0 + rows; r += 8) {
        const float* x = h1 + (size_t)r * 1024;
        float acc = 0.0f;
        for (int k0 = 0; k0 < 1024; k0 += 32) {
            float xv = x[k0 + lane];
#pragma unroll
            for (int kk = 0; kk < 32; kk++) {
                float xs = __shfl_sync(0xffffffffu, xv, kk);
                acc += xs * s[(k0 + kk) * 32 + lane];
            }
        }
        feats[(size_t)r * 32 + lane] = acc + bias;
    }
}

// ---------------- CRF forward (one warp per batch, lane = tag) ----------------
__global__ __launch_bounds__(32) void k_crf(
    const float* __restrict__ feats, const float* __restrict__ trans,
    const int* __restrict__ tokens, float* __restrict__ logz)
{
    __shared__ float s_tr[32 * 33];
    int lane = threadIdx.x;
    for (int i = lane; i < 1024; i += 32)
        s_tr[(i >> 5) * 33 + (i & 31)] = trans[i];
    __syncwarp();
    int b = blockIdx.x;

    float alpha = (lane == STARTT) ? 0.0f : NEGV;
    for (int t = 0; t < TT; t++) {
        float emit = feats[(size_t)(t * BB + b) * 32 + lane];
        int m = tokens[t * BB + b] > 0;
        float v[32];
        float mx = -3.4e38f;
#pragma unroll
        for (int k = 0; k < 32; k++) {
            float ak = __shfl_sync(0xffffffffu, alpha, k);
            v[k] = ak + s_tr[lane * 33 + k];
            mx = fmaxf(mx, v[k]);
        }
        float ssum = 0.0f;
#pragma unroll
        for (int k = 0; k < 32; k++) ssum += __expf(v[k] - mx);
        float nv = mx + __logf(ssum) + emit;
        alpha = m ? nv : alpha;
    }
    float val = alpha + s_tr[ENDT * 33 + lane];
    float mx = val;
#pragma unroll
    for (int o = 16; o; o >>= 1) mx = fmaxf(mx, __shfl_xor_sync(0xffffffffu, mx, o));
    float ss = __expf(val - mx);
#pragma unroll
    for (int o = 16; o; o >>= 1) ss += __shfl_xor_sync(0xffffffffu, ss, o);
    if (lane == 0) logz[b] = mx + __logf(ss);
}

// ---------------- gold score + final reduction ----------------
__global__ void k_final(
    const int* __restrict__ tags, const int* __restrict__ tokens,
    const float* __restrict__ trans, const float* __restrict__ feats,
    const float* __restrict__ logz, const int* __restrict__ lengths,
    float* __restrict__ out)
{
    __shared__ float red[BB];
    int b = threadIdx.x;
    float gold = 0.0f;
    int prev = STARTT;
    for (int t = 0; t < TT; t++) {
        int cur = tags[t * BB + b];
        float m = tokens[t * BB + b] > 0 ? 1.0f : 0.0f;
        gold += m * (trans[cur * 32 + prev] + feats[(size_t)(t * BB + b) * 32 + cur]);
        prev = cur;
    }
    gold += trans[ENDT * 32 + prev];
    red[b] = (logz[b] - gold) / (float)lengths[b];
    __syncthreads();
    if (b == 0) {
        float s = 0.0f;
        for (int i = 0; i < BB; i++) s += red[i];
        out[0] = s;
    }
}

// ---------------- launch ----------------
extern "C" void kernel_launch(void* const* d_in, const int* in_sizes, int n_in,
                              void* d_out, int out_size)
{
    const int*   tokens = (const int*)d_in[0];
    const int*   tags   = (const int*)d_in[1];
    const int*   lens   = (const int*)d_in[2];
    const float* embed  = (const float*)d_in[3];
    const float* wih0   = (const float*)d_in[4];
    const float* whh0   = (const float*)d_in[5];
    const float* b0     = (const float*)d_in[6];
    const float* wih1   = (const float*)d_in[7];
    const float* whh1   = (const float*)d_in[8];
    const float* b1     = (const float*)d_in[9];
    const float* lin_w  = (const float*)d_in[10];
    const float* lin_b  = (const float*)d_in[11];
    const float* trans  = (const float*)d_in[12];
    float* out = (float*)d_out;

    void *p;
    cudaGetSymbolAddress(&p, g_xp);    float* xp    = (float*)p;
    cudaGetSymbolAddress(&p, g_h0);    float* h0    = (float*)p;
    cudaGetSymbolAddress(&p, g_h1);    float* h1    = (float*)p;
    cudaGetSymbolAddress(&p, g_feats); float* feats = (float*)p;
    cudaGetSymbolAddress(&p, g_logz);  float* logz  = (float*)p;

    const int LSTM_SMEM = 32768 * 4 + 2 * 2048 * 16 + 64;  // 196672 B
    cudaFuncSetAttribute(k_lstm, cudaFuncAttributeMaxDynamicSharedMemorySize, LSTM_SMEM);
    cudaFuncSetAttribute(k_feats, cudaFuncAttributeMaxDynamicSharedMemorySize, 131072);

    dim3 gg(NG / 128, TB / 128);   // (32, 128)

    // layer 0
    k_gemm<EE, true><<<gg, 512>>>(embed, tokens, wih0, b0, xp);
    k_lstm<<<128, 256, LSTM_SMEM>>>(xp, whh0, h0);

    // layer 1
    k_gemm<1024, false><<<gg, 512>>>(h0, tokens, wih1, b1, xp);
    k_lstm<<<128, 256, LSTM_SMEM>>>(xp, whh1, h1);

    // emissions
    k_feats<<<128, 256, 131072>>>(h1, lin_w, lin_b, feats);

    // CRF partition function
    k_crf<<<BB, 32>>>(feats, trans, tokens, logz);

    // gold + loss
    k_final<<<1, BB>>>(tags, tokens, trans, feats, logz, lens, out);
}

// round 6
// speedup vs baseline: 2.5070x; 1.0050x over previous
#include <cuda_runtime.h>
#include <cuda_bf16.h>
#include <cstdint>

typedef unsigned long long ull;

// ---------------- problem constants ----------------
#define TT   256
#define BB   64
#define EE   512
#define HH   512
#define KK   32
#define TB   (TT*BB)        // 16384
#define NG   4096           // 2 dirs * 4H gate columns
#define STARTT 30
#define ENDT   31
#define NEGV  (-100000.0f)

#define HBYTES  (BB*HH*4)   // 131072
#define CHUNKB  8192        // 4 rows * 512 * 4B

// ---------------- device scratch (static, no cudaMalloc) ----------------
__device__ float g_xp[(size_t)TB * NG];        // reused by both layers
__device__ float g_h0[(size_t)TB * 1024];      // layer0 output (fwd|bwd)
__device__ float g_h1[(size_t)TB * 1024];      // layer1 output
__device__ float g_feats[(size_t)TB * KK];     // emissions
__device__ float g_hbuf[2 * 2 * BB * HH];      // [parity][dir][b][j]
__device__ float g_logz[BB];

// per-direction grid barrier state
__device__ unsigned g_cnt2[2] = {0, 0};
__device__ unsigned g_gen2[2] = {0, 0};

// ---------------- helpers ----------------
__device__ __forceinline__ void ffma2(ull &d, ull a, ull b) {
    asm("fma.rn.f32x2 %0, %1, %2, %0;" : "+l"(d) : "l"(a), "l"(b));
}
__device__ __forceinline__ float2 unpack2(ull v) {
    float2 r;
    asm("mov.b64 {%0, %1}, %2;" : "=f"(r.x), "=f"(r.y) : "l"(v));
    return r;
}
__device__ __forceinline__ ull pk2(float lo, float hi) {
    ull v;
    asm("mov.b64 %0, {%1,%2};" : "=l"(v) : "f"(lo), "f"(hi));
    return v;
}
__device__ __forceinline__ float sigmoidf_(float x) { return 1.0f / (1.0f + expf(-x)); }

__device__ __forceinline__ uint32_t s2u(const void* p) {
    uint32_t a;
    asm("{ .reg .u64 t; cvta.to.shared.u64 t, %1; cvt.u32.u64 %0, t; }" : "=r"(a) : "l"(p));
    return a;
}
__device__ __forceinline__ void mwait(uint32_t mbar, uint32_t phase) {
    asm volatile(
        "{\n\t.reg .pred P;\n"
        "W%=:\n\t"
        "mbarrier.try_wait.parity.acquire.cta.shared::cta.b64 P, [%0], %1, 0x989680;\n\t"
        "@P bra D%=;\n\t"
        "bra W%=;\n"
        "D%=:\n\t}"
        :: "r"(mbar), "r"(phase) : "memory");
}

__device__ __forceinline__ void grid_barrier(int dir) {
    __syncthreads();
    if (threadIdx.x == 0) {
        __threadfence();
        unsigned my = *((volatile unsigned*)&g_gen2[dir]);
        if (atomicAdd(&g_cnt2[dir], 1u) == 63u) {
            g_cnt2[dir] = 0;
            __threadfence();
            *((volatile unsigned*)&g_gen2[dir]) = my + 1;
        } else {
            while (*((volatile unsigned*)&g_gen2[dir]) == my) { }
        }
        __threadfence();
    }
    __syncthreads();
}

// ---------------- SGEMM: C[16384][4096] = A[M][KD]*Bw[4096][KD]^T + bias ------
// 128x128 tile, 512 threads, f32x2. Loaders pack k-pairs in registers (STS.64,
// conflict-free 4*kp banking). Bs consumer XOR-swizzled -> conflict-free LDS.128.
template<int KD, bool GATHER>
__global__ __launch_bounds__(512) void k_gemm(
    const float* __restrict__ A, const int* __restrict__ tok,
    const float* __restrict__ Bw, const float* __restrict__ bias,
    float* __restrict__ C)
{
    __shared__ ull As[8 * 130];
    __shared__ ull Bs[8 * 130];
    int tid = threadIdx.x;
    int n0 = blockIdx.x * 128, m0 = blockIdx.y * 128;
    int tn = tid & 15, tm = tid >> 4;

    int kp = tid & 7, rr = tid >> 3;   // rr 0..63
    const float* aro[2];
    const float* bro[2];
    int sA[2], sB[2];
#pragma unroll
    for (int i = 0; i < 2; i++) {
        int r = rr + 64 * i;
        aro[i] = (GATHER ? A + (size_t)tok[m0 + r] * KD
                         : A + (size_t)(m0 + r) * KD) + 2 * kp;
        bro[i] = Bw + (size_t)(n0 + r) * KD + 2 * kp;
        sA[i] = kp * 130 + r;
        int t8 = r >> 3, j = (r >> 1) & 3, sw = (r >> 4) & 3;
        sB[i] = kp * 130 + (t8 * 4 + (j ^ sw)) * 2 + (r & 1);
    }

    float bb[8];
#pragma unroll
    for (int j = 0; j < 8; j++) bb[j] = bias[n0 + tn * 8 + j];

    ull acc[4][8];
#pragma unroll
    for (int i = 0; i < 4; i++)
#pragma unroll
        for (int j = 0; j < 8; j++) acc[i][j] = 0ull;

    float2 pa[2], pb[2];
#pragma unroll
    for (int i = 0; i < 2; i++) { pa[i] = *(const float2*)aro[i]; pb[i] = *(const float2*)bro[i]; }

    int swc = (tn >> 1) & 3;

    for (int k0 = 0; k0 < KD; k0 += 16) {
#pragma unroll
        for (int i = 0; i < 2; i++) {
            As[sA[i]] = pk2(pa[i].x, pa[i].y);
            Bs[sB[i]] = pk2(pb[i].x, pb[i].y);
        }
        __syncthreads();
        if (k0 + 16 < KD) {
#pragma unroll
            for (int i = 0; i < 2; i++) {
                pa[i] = *(const float2*)(aro[i] + k0 + 16);
                pb[i] = *(const float2*)(bro[i] + k0 + 16);
            }
        }
#pragma unroll
        for (int k2 = 0; k2 < 8; k2++) {
            ull a2[4], b2[8];
            {
                ulonglong2 v0 = *(const ulonglong2*)&As[k2 * 130 + tm * 4];
                ulonglong2 v1 = *(const ulonglong2*)&As[k2 * 130 + tm * 4 + 2];
                a2[0] = v0.x; a2[1] = v0.y; a2[2] = v1.x; a2[3] = v1.y;
            }
#pragma unroll
            for (int j = 0; j < 4; j++) {
                ulonglong2 v = *(const ulonglong2*)&Bs[k2 * 130 + (tn * 4 + (j ^ swc)) * 2];
                b2[2 * j] = v.x; b2[2 * j + 1] = v.y;
            }
#pragma unroll
            for (int i = 0; i < 4; i++)
#pragma unroll
                for (int j = 0; j < 8; j++)
                    ffma2(acc[i][j], a2[i], b2[j]);
        }
        __syncthreads();
    }
#pragma unroll
    for (int i = 0; i < 4; i++) {
        int m = m0 + tm * 4 + i;
        float o[8];
#pragma unroll
        for (int j = 0; j < 8; j++) {
            float2 u = unpack2(acc[i][j]);
            o[j] = u.x + u.y + bb[j];
        }
        *(float4*)&C[(size_t)m * NG + n0 + tn * 8]     = make_float4(o[0], o[1], o[2], o[3]);
        *(float4*)&C[(size_t)m * NG + n0 + tn * 8 + 4] = make_float4(o[4], o[5], o[6], o[7]);
    }
}

// ---------------- persistent BiLSTM layer kernel ----------------
// grid = 128 CTAs (1/SM), 512 threads (16 warps, 4/SMSP). CTA c: dir = c>>6,
// owns h-cols j0..j0+7. Warp w owns batch rows w*4..w*4+3 (one 8KB h-chunk,
// own mbarrier). Weights resident in SMEM in two gate-pair planes with the
// per-k-quarter ROTATION swizzle (q2 = (q + 4*ks) & 63) so the 4 ks lanes of
// each h LDS.128 hit disjoint bank groups. Cross-ks reduction via shfl_xor.
__global__ __launch_bounds__(512) void k_lstm(
    const float* __restrict__ xp,   // [TB][4096]: dir*2048 + gt*512 + j (bias incl)
    const float* __restrict__ whh,  // raw [2][2048][512]
    float* __restrict__ hout)       // [TB][1024]: dir*512 + j
{
    extern __shared__ float sm[];
    float* h_s = sm;                                  // 32768 floats (128KB)
    ulonglong2* wA = (ulonglong2*)(sm + 32768);       // gates 0,1: 2048 slots (32KB)
    ulonglong2* wB = wA + 2048;                       // gates 2,3: 2048 slots (32KB)
    ull* mbar = (ull*)(wB + 2048);                    // 16 mbarriers

    int tid = threadIdx.x, cta = blockIdx.x;
    int dir = cta >> 6, j0 = (cta & 63) * 8;
    int lane = tid & 31, w = tid >> 5;                // 16 warps
    int c4 = lane & 7, ks = (lane >> 3) & 3;

    uint32_t mbar_u = s2u(mbar), hdst_u = s2u(h_s);
    if (tid < 16)
        asm volatile("mbarrier.init.shared.b64 [%0], 1;" :: "r"(mbar_u + tid * 8));

    // stage weights with per-quarter rotation: slot (kq, k2, c4) holds k-pair
    // kq*64 + ((k2 + 4*kq) & 63). Plane A = gates 0,1; plane B = gates 2,3.
    const float* W = whh + (size_t)dir * 2048 * 512;
    for (int f = tid; f < 2048; f += 512) {
        int fc = f & 7, k2 = (f >> 3) & 63, kq = f >> 9;
        int k2r = (k2 + 4 * kq) & 63;
        int k = kq * 128 + k2r * 2;
        int jc = j0 + fc;
        const float* w0 = W + (size_t)jc * 512 + k;            // gate 0 row jc
        ull a0 = pk2(w0[0],                 w0[1]);
        ull a1 = pk2(w0[512 * 512],         w0[512 * 512 + 1]);
        ull b0 = pk2(w0[1024 * 512],        w0[1024 * 512 + 1]);
        ull b1 = pk2(w0[1536 * 512],        w0[1536 * 512 + 1]);
        ulonglong2 va; va.x = a0; va.y = a1;
        ulonglong2 vb; vb.x = b0; vb.y = b1;
        wA[f] = va;
        wB[f] = vb;
    }
    __syncthreads();

    const ulonglong2* wAp = wA + ks * 512 + c4;
    const ulonglong2* wBp = wB + ks * 512 + c4;
    const float* hb = h_s + (w * 4) * 512 + ks * 128;
    int rot = ks * 4;

    float creg[4];
#pragma unroll
    for (int i = 0; i < 4; i++) creg[i] = 0.0f;

    for (int s = 0; s < TT; s++) {
        int t = dir ? (TT - 1 - s) : s;
        int par = s & 1;

        // kick off 16 independent row-chunk copies (producer writes fenced by
        // the per-direction grid barrier at the end of the previous step)
        if (s > 0 && tid < 16) {
            const float* src = g_hbuf + (size_t)(par * 2 + dir) * BB * HH + tid * 2048;
            uint32_t mb = mbar_u + tid * 8;
            asm volatile("mbarrier.arrive.expect_tx.shared.b64 _, [%0], %1;"
                         :: "r"(mb), "r"((uint32_t)CHUNKB));
            asm volatile("cp.async.bulk.shared::cta.global.mbarrier::complete_tx::bytes [%0], [%1], %2, [%3];"
                         :: "r"(hdst_u + (uint32_t)tid * CHUNKB), "l"(src),
                            "r"((uint32_t)CHUNKB), "r"(mb) : "memory");
        }

        // prefetch xp while copies are in flight (only ks==0 threads use it)
        float xpre[4][4];
        if (ks == 0) {
#pragma unroll
            for (int i = 0; i < 4; i++) {
                int b = w * 4 + i;
                const float* xr = xp + (size_t)(t * BB + b) * NG + dir * 2048 + j0 + c4;
                xpre[i][0] = xr[0];
                xpre[i][1] = xr[512];
                xpre[i][2] = xr[1024];
                xpre[i][3] = xr[1536];
            }
        }

        float af[4][4];
        if (s > 0) {
            // wait only for THIS warp's row chunk
            mwait(mbar_u + w * 8, (s - 1) & 1);

            ull acc[4][4];
#pragma unroll
            for (int i = 0; i < 4; i++)
#pragma unroll
                for (int g = 0; g < 4; g++) acc[i][g] = 0ull;

#pragma unroll 4
            for (int q = 0; q < 64; q += 2) {
                int q2 = (q + rot) & 63;     // rotated k-pair (matches staged weights)
                ulonglong2 wa0 = wAp[q * 8];
                ulonglong2 wb0 = wBp[q * 8];
                ulonglong2 wa1 = wAp[(q + 1) * 8];
                ulonglong2 wb1 = wBp[(q + 1) * 8];
#pragma unroll
                for (int i = 0; i < 4; i++) {
                    ulonglong2 h2 = *(const ulonglong2*)(hb + i * 512 + q2 * 2);
                    ffma2(acc[i][0], h2.x, wa0.x);
                    ffma2(acc[i][1], h2.x, wa0.y);
                    ffma2(acc[i][2], h2.x, wb0.x);
                    ffma2(acc[i][3], h2.x, wb0.y);
                    ffma2(acc[i][0], h2.y, wa1.x);
                    ffma2(acc[i][1], h2.y, wa1.y);
                    ffma2(acc[i][2], h2.y, wb1.x);
                    ffma2(acc[i][3], h2.y, wb1.y);
                }
            }
            // cross-ks reduction: lanes (ks in bits 3,4 of lane id)
#pragma unroll
            for (int i = 0; i < 4; i++)
#pragma unroll
                for (int g = 0; g < 4; g++) {
                    float2 u = unpack2(acc[i][g]);
                    float v = u.x + u.y;
                    v += __shfl_xor_sync(0xffffffffu, v, 8);
                    v += __shfl_xor_sync(0xffffffffu, v, 16);
                    af[i][g] = v;
                }
        }

        if (ks == 0) {
#pragma unroll
            for (int i = 0; i < 4; i++) {
                int b = w * 4 + i;
                float p0 = xpre[i][0], p1 = xpre[i][1], p2 = xpre[i][2], p3 = xpre[i][3];
                if (s > 0) { p0 += af[i][0]; p1 += af[i][1]; p2 += af[i][2]; p3 += af[i][3]; }
                float ig = sigmoidf_(p0);
                float fg = sigmoidf_(p1);
                float gg = tanhf(p2);
                float og = sigmoidf_(p3);
                float c = fg * creg[i] + ig * gg;
                creg[i] = c;
                float h = og * tanhf(c);
                int j = j0 + c4;
                g_hbuf[(size_t)(((par ^ 1) * 2 + dir) * BB + b) * HH + j] = h;
                hout[(size_t)(t * BB + b) * 1024 + dir * 512 + j] = h;
            }
        }
        grid_barrier(dir);
    }
}

// ---------------- emission features: feats = h1 @ lin_w^T + lin_b ----------------
__global__ __launch_bounds__(256) void k_feats(
    const float* __restrict__ h1, const float* __restrict__ lin_w,
    const float* __restrict__ lin_b, float* __restrict__ feats)
{
    extern __shared__ float s[];  // [1024][32] transposed lin_w
    int tid = threadIdx.x;
    for (int i = tid; i < 32 * 1024; i += 256) {
        int c = i & 31, k = i >> 5;
        s[k * 32 + c] = lin_w[c * 1024 + k];
    }
    float bias = lin_b[tid & 31];
    __syncthreads();
    int warp = tid >> 5, lane = tid & 31;
    int rows = TB / gridDim.x;
    int r0 = blockIdx.x * rows;
    for (int r = r0 + warp; r < r0 + rows; r += 8) {
        const float* x = h1 + (size_t)r * 1024;
        float acc = 0.0f;
        for (int k0 = 0; k0 < 1024; k0 += 32) {
            float xv = x[k0 + lane];
#pragma unroll
            for (int kk = 0; kk < 32; kk++) {
                float xs = __shfl_sync(0xffffffffu, xv, kk);
                acc += xs * s[(k0 + kk) * 32 + lane];
            }
        }
        feats[(size_t)r * 32 + lane] = acc + bias;
    }
}

// ---------------- CRF forward (one warp per batch, lane = tag) ----------------
__global__ __launch_bounds__(32) void k_crf(
    const float* __restrict__ feats, const float* __restrict__ trans,
    const int* __restrict__ tokens, float* __restrict__ logz)
{
    __shared__ float s_tr[32 * 33];
    int lane = threadIdx.x;
    for (int i = lane; i < 1024; i += 32)
        s_tr[(i >> 5) * 33 + (i & 31)] = trans[i];
    __syncwarp();
    int b = blockIdx.x;

    float alpha = (lane == STARTT) ? 0.0f : NEGV;
    for (int t = 0; t < TT; t++) {
        float emit = feats[(size_t)(t * BB + b) * 32 + lane];
        int m = tokens[t * BB + b] > 0;
        float v[32];
        float mx = -3.4e38f;
#pragma unroll
        for (int k = 0; k < 32; k++) {
            float ak = __shfl_sync(0xffffffffu, alpha, k);
            v[k] = ak + s_tr[lane * 33 + k];
            mx = fmaxf(mx, v[k]);
        }
        float ssum = 0.0f;
#pragma unroll
        for (int k = 0; k < 32; k++) ssum += __expf(v[k] - mx);
        float nv = mx + __logf(ssum) + emit;
        alpha = m ? nv : alpha;
    }
    float val = alpha + s_tr[ENDT * 33 + lane];
    float mx = val;
#pragma unroll
    for (int o = 16; o; o >>= 1) mx = fmaxf(mx, __shfl_xor_sync(0xffffffffu, mx, o));
    float ss = __expf(val - mx);
#pragma unroll
    for (int o = 16; o; o >>= 1) ss += __shfl_xor_sync(0xffffffffu, ss, o);
    if (lane == 0) logz[b] = mx + __logf(ss);
}

// ---------------- gold score + final reduction ----------------
__global__ void k_final(
    const int* __restrict__ tags, const int* __restrict__ tokens,
    const float* __restrict__ trans, const float* __restrict__ feats,
    const float* __restrict__ logz, const int* __restrict__ lengths,
    float* __restrict__ out)
{
    __shared__ float red[BB];
    int b = threadIdx.x;
    float gold = 0.0f;
    int prev = STARTT;
    for (int t = 0; t < TT; t++) {
        int cur = tags[t * BB + b];
        float m = tokens[t * BB + b] > 0 ? 1.0f : 0.0f;
        gold += m * (trans[cur * 32 + prev] + feats[(size_t)(t * BB + b) * 32 + cur]);
        prev = cur;
    }
    gold += trans[ENDT * 32 + prev];
    red[b] = (logz[b] - gold) / (float)lengths[b];
    __syncthreads();
    if (b == 0) {
        float s = 0.0f;
        for (int i = 0; i < BB; i++) s += red[i];
        out[0] = s;
    }
}

// ---------------- launch ----------------
extern "C" void kernel_launch(void* const* d_in, const int* in_sizes, int n_in,
                              void* d_out, int out_size)
{
    const int*   tokens = (const int*)d_in[0];
    const int*   tags   = (const int*)d_in[1];
    const int*   lens   = (const int*)d_in[2];
    const float* embed  = (const float*)d_in[3];
    const float* wih0   = (const float*)d_in[4];
    const float* whh0   = (const float*)d_in[5];
    const float* b0     = (const float*)d_in[6];
    const float* wih1   = (const float*)d_in[7];
    const float* whh1   = (const float*)d_in[8];
    const float* b1     = (const float*)d_in[9];
    const float* lin_w  = (const float*)d_in[10];
    const float* lin_b  = (const float*)d_in[11];
    const float* trans  = (const float*)d_in[12];
    float* out = (float*)d_out;

    void *p;
    cudaGetSymbolAddress(&p, g_xp);    float* xp    = (float*)p;
    cudaGetSymbolAddress(&p, g_h0);    float* h0    = (float*)p;
    cudaGetSymbolAddress(&p, g_h1);    float* h1    = (float*)p;
    cudaGetSymbolAddress(&p, g_feats); float* feats = (float*)p;
    cudaGetSymbolAddress(&p, g_logz);  float* logz  = (float*)p;

    const int LSTM_SMEM = 32768 * 4 + 2 * 2048 * 16 + 128;  // 196736 B
    cudaFuncSetAttribute(k_lstm, cudaFuncAttributeMaxDynamicSharedMemorySize, LSTM_SMEM);
    cudaFuncSetAttribute(k_feats, cudaFuncAttributeMaxDynamicSharedMemorySize, 131072);

    dim3 gg(NG / 128, TB / 128);   // (32, 128)

    // layer 0
    k_gemm<EE, true><<<gg, 512>>>(embed, tokens, wih0, b0, xp);
    k_lstm<<<128, 512, LSTM_SMEM>>>(xp, whh0, h0);

    // layer 1
    k_gemm<1024, false><<<gg, 512>>>(h0, tokens, wih1, b1, xp);
    k_lstm<<<128, 512, LSTM_SMEM>>>(xp, whh1, h1);

    // emissions
    k_feats<<<128, 256, 131072>>>(h1, lin_w, lin_b, feats);

    // CRF partition function
    k_crf<<<BB, 32>>>(feats, trans, tokens, logz);

    // gold + loss
    k_final<<<1, BB>>>(tags, tokens, trans, feats, logz, lens, out);
}